// round 1
// baseline (speedup 1.0000x reference)
#include <cuda_runtime.h>
#include <math.h>
#include <stdint.h>

// ---------------- problem constants ----------------
#define BATCH   2
#define DSZ     28            // D = H = W
#define WS      7
#define SHIFT_  3
#define CDIM    192
#define HEADS   6
#define HD      32
#define NTOK    343            // WS^3
#define NWIN    64             // windows per batch elem
#define TOTWIN  128            // BATCH * NWIN
#define TOK     43904          // BATCH * 28^3
#define HID     768
#define NN      117649         // 343*343
#define SCALE   0.17677669529663687f   // 32^-0.5

// ---------------- scratch (device globals; no allocation allowed) ----------------
__device__ float g_xw  [TOK * CDIM];        // LN1 + shift + window-partitioned
__device__ float g_qkv [TOK * 3 * CDIM];    // qkv gemm out (windowed row order)
__device__ float g_bias6[HEADS * NN];       // rel bias expanded per head
__device__ float g_attn[TOK * CDIM];        // attention out (windowed row order)
__device__ float g_proj[TOK * CDIM];        // proj gemm out (windowed row order)
__device__ float g_xres[TOK * CDIM];        // shortcut + attn branch (token order)
__device__ float g_ln2 [TOK * CDIM];        // LN2 out (token order)
__device__ float g_h1  [TOK * HID];         // fc1+gelu out

// ---------------- helpers ----------------
__device__ __forceinline__ float warpSum(float v) {
#pragma unroll
    for (int o = 16; o; o >>= 1) v += __shfl_xor_sync(0xffffffffu, v, o);
    return v;
}
__device__ __forceinline__ float warpMax(float v) {
#pragma unroll
    for (int o = 16; o; o >>= 1) v = fmaxf(v, __shfl_xor_sync(0xffffffffu, v, o));
    return v;
}

// token index -> windowed row index (after -SHIFT cyclic shift + partition)
__device__ __forceinline__ int token_to_winrow(int t) {
    int b   = t / (DSZ * DSZ * DSZ);
    int rem = t - b * (DSZ * DSZ * DSZ);
    int dd  = rem / (DSZ * DSZ);
    int hh  = (rem / DSZ) % DSZ;
    int ww  = rem % DSZ;
    int i = (dd + DSZ - SHIFT_) % DSZ;
    int j = (hh + DSZ - SHIFT_) % DSZ;
    int k = (ww + DSZ - SHIFT_) % DSZ;
    int win = (i / WS) * 16 + (j / WS) * 4 + (k / WS);
    int n   = (i % WS) * 49 + (j % WS) * 7 + (k % WS);
    return (b * NWIN + win) * NTOK + n;
}

// ---------------- kernel 1: expand relative-position bias per head ----------------
__global__ void bias_pre_kernel(const int* __restrict__ rel_index,
                                const float* __restrict__ table,
                                float* __restrict__ bias6) {
    int ij = blockIdx.x * 256 + threadIdx.x;
    if (ij >= NN) return;
    int r = rel_index[ij];
#pragma unroll
    for (int h = 0; h < HEADS; h++)
        bias6[h * NN + ij] = table[r * HEADS + h];
}

// ---------------- kernel 2: LN1 + shift + window partition ----------------
__global__ __launch_bounds__(CDIM) void ln1_kernel(const float* __restrict__ x,
                                                   const float* __restrict__ g,
                                                   const float* __restrict__ b,
                                                   float* __restrict__ xw) {
    __shared__ float red[12];
    int t = blockIdx.x;
    int c = threadIdx.x;
    float v = x[(size_t)t * CDIM + c];

    float s  = warpSum(v);
    float s2 = warpSum(v * v);
    int w = c >> 5;
    if ((c & 31) == 0) { red[w] = s; red[6 + w] = s2; }
    __syncthreads();
    float ts = 0.f, ts2 = 0.f;
#pragma unroll
    for (int i = 0; i < 6; i++) { ts += red[i]; ts2 += red[6 + i]; }
    float mean = ts * (1.0f / CDIM);
    float var  = ts2 * (1.0f / CDIM) - mean * mean;
    float o = (v - mean) * rsqrtf(var + 1e-5f) * g[c] + b[c];

    int row = token_to_winrow(t);
    xw[(size_t)row * CDIM + c] = o;
}

// ---------------- kernel 3: generic fp32 NT GEMM (C = A @ B^T + bias, epilogue) ----------------
// A: (M,K) row-major; B: (N,K) row-major. M%64==0, N%64==0, K%16==0.
// epi: 0 = none, 1 = exact gelu, 2 = add resid
__global__ __launch_bounds__(256) void gemm_nt_kernel(
    const float* __restrict__ A, const float* __restrict__ Bm,
    const float* __restrict__ bias, const float* __restrict__ resid,
    float* __restrict__ Cm, int M, int N, int K, int epi)
{
    __shared__ float As[16][65];
    __shared__ float Bs[16][65];
    const int bm = blockIdx.y * 64;
    const int bn = blockIdx.x * 64;
    const int tid = threadIdx.x;
    const int tr = tid >> 4;       // 0..15
    const int tc = tid & 15;       // 0..15
    float acc[4][4] = {};

    const float* Ab = A  + (size_t)bm * K;
    const float* Bb = Bm + (size_t)bn * K;
    const int lr = tid >> 2;           // 0..63
    const int lc = (tid & 3) * 4;      // 0,4,8,12

    for (int k0 = 0; k0 < K; k0 += 16) {
        float4 av = *(const float4*)(Ab + (size_t)lr * K + k0 + lc);
        As[lc + 0][lr] = av.x; As[lc + 1][lr] = av.y;
        As[lc + 2][lr] = av.z; As[lc + 3][lr] = av.w;
        float4 bv = *(const float4*)(Bb + (size_t)lr * K + k0 + lc);
        Bs[lc + 0][lr] = bv.x; Bs[lc + 1][lr] = bv.y;
        Bs[lc + 2][lr] = bv.z; Bs[lc + 3][lr] = bv.w;
        __syncthreads();
#pragma unroll
        for (int k = 0; k < 16; k++) {
            float a0 = As[k][tr * 4 + 0], a1 = As[k][tr * 4 + 1];
            float a2 = As[k][tr * 4 + 2], a3 = As[k][tr * 4 + 3];
            float b0 = Bs[k][tc * 4 + 0], b1 = Bs[k][tc * 4 + 1];
            float b2 = Bs[k][tc * 4 + 2], b3 = Bs[k][tc * 4 + 3];
            acc[0][0] += a0 * b0; acc[0][1] += a0 * b1; acc[0][2] += a0 * b2; acc[0][3] += a0 * b3;
            acc[1][0] += a1 * b0; acc[1][1] += a1 * b1; acc[1][2] += a1 * b2; acc[1][3] += a1 * b3;
            acc[2][0] += a2 * b0; acc[2][1] += a2 * b1; acc[2][2] += a2 * b2; acc[2][3] += a2 * b3;
            acc[3][0] += a3 * b0; acc[3][1] += a3 * b1; acc[3][2] += a3 * b2; acc[3][3] += a3 * b3;
        }
        __syncthreads();
    }

#pragma unroll
    for (int i = 0; i < 4; i++) {
        int row = bm + tr * 4 + i;
#pragma unroll
        for (int j = 0; j < 4; j++) {
            int col = bn + tc * 4 + j;
            float v = acc[i][j] + bias[col];
            if (epi == 1) {
                v = 0.5f * v * (1.0f + erff(v * 0.7071067811865476f));
            } else if (epi == 2) {
                v += resid[(size_t)row * N + col];
            }
            Cm[(size_t)row * N + col] = v;
        }
    }
}

// ---------------- kernel 4: attention (one block per window*head) ----------------
// smem layout: ks[343*33] | vs[343*33] | sc[343] | qrow[32] | part[256]
__global__ __launch_bounds__(256) void attn_kernel(
    const float* __restrict__ qkv, const float* __restrict__ bias6,
    const float* __restrict__ mask, float* __restrict__ out)
{
    extern __shared__ float sm[];
    float* ks   = sm;
    float* vs   = ks + NTOK * 33;
    float* sc   = vs + NTOK * 33;
    float* qrow = sc + NTOK;
    float* part = qrow + 32;
    __shared__ float red[8];

    const int bx  = blockIdx.x;
    const int w   = bx / HEADS;
    const int h   = bx - w * HEADS;
    const int mw  = w % NWIN;            // mask window index
    const int tid = threadIdx.x;

    const float* base = qkv + (size_t)w * NTOK * (3 * CDIM) + h * HD;
    // load K (offset CDIM) and V (offset 2*CDIM) into padded smem
    for (int idx = tid; idx < NTOK * HD; idx += 256) {
        int j = idx >> 5, d = idx & 31;
        const float* rowp = base + (size_t)j * (3 * CDIM);
        ks[j * 33 + d] = rowp[CDIM + d];
        vs[j * 33 + d] = rowp[2 * CDIM + d];
    }
    __syncthreads();

    const float* biasrow0 = bias6 + (size_t)h * NN;
    const float* maskrow0 = mask + (size_t)mw * NN;

    for (int i = 0; i < NTOK; i++) {
        if (tid < 32) qrow[tid] = base[(size_t)i * (3 * CDIM) + tid];
        __syncthreads();

        // scores
        float lmax = -1e30f;
        const float* brow = biasrow0 + (size_t)i * NTOK;
        const float* mrow = maskrow0 + (size_t)i * NTOK;
        for (int j = tid; j < NTOK; j += 256) {
            float s = 0.f;
            const float* kj = ks + j * 33;
#pragma unroll
            for (int d = 0; d < HD; d++) s += qrow[d] * kj[d];
            s = s * SCALE + brow[j] + mrow[j];
            sc[j] = s;
            lmax = fmaxf(lmax, s);
        }
        // block max
        {
            float wv = warpMax(lmax);
            if ((tid & 31) == 0) red[tid >> 5] = wv;
            __syncthreads();
            lmax = red[0];
#pragma unroll
            for (int r = 1; r < 8; r++) lmax = fmaxf(lmax, red[r]);
        }
        __syncthreads();
        // exp + sum
        float lsum = 0.f;
        for (int j = tid; j < NTOK; j += 256) {
            float e = __expf(sc[j] - lmax);
            sc[j] = e;
            lsum += e;
        }
        {
            float wv = warpSum(lsum);
            if ((tid & 31) == 0) red[tid >> 5] = wv;
            __syncthreads();
            lsum = 0.f;
#pragma unroll
            for (int r = 0; r < 8; r++) lsum += red[r];
        }
        __syncthreads();           // sc[] fully written & visible
        float inv = __frcp_rn(lsum);

        // P @ V : 8 chunks of ~43 keys, 32 dims
        {
            int d = tid & 31, c = tid >> 5;
            int j0 = c * 43;
            int j1 = j0 + 43; if (j1 > NTOK) j1 = NTOK;
            float p = 0.f;
            for (int j = j0; j < j1; j++) p += sc[j] * vs[j * 33 + d];
            part[c * 32 + d] = p;
        }
        __syncthreads();
        if (tid < 32) {
            float o = 0.f;
#pragma unroll
            for (int c = 0; c < 8; c++) o += part[c * 32 + tid];
            out[((size_t)w * NTOK + i) * CDIM + h * HD + tid] = o * inv;
        }
        __syncthreads();           // protect sc/qrow/part for next row
    }
}

// ---------------- kernel 5: window reverse + unshift + residual + LN2 ----------------
__global__ __launch_bounds__(CDIM) void ln2res_kernel(const float* __restrict__ x,
                                                      const float* __restrict__ proj,
                                                      const float* __restrict__ g,
                                                      const float* __restrict__ b,
                                                      float* __restrict__ xres,
                                                      float* __restrict__ ln2o) {
    __shared__ float red[12];
    int t = blockIdx.x;
    int c = threadIdx.x;
    int row = token_to_winrow(t);
    float v = x[(size_t)t * CDIM + c] + proj[(size_t)row * CDIM + c];
    xres[(size_t)t * CDIM + c] = v;

    float s  = warpSum(v);
    float s2 = warpSum(v * v);
    int w = c >> 5;
    if ((c & 31) == 0) { red[w] = s; red[6 + w] = s2; }
    __syncthreads();
    float ts = 0.f, ts2 = 0.f;
#pragma unroll
    for (int i = 0; i < 6; i++) { ts += red[i]; ts2 += red[6 + i]; }
    float mean = ts * (1.0f / CDIM);
    float var  = ts2 * (1.0f / CDIM) - mean * mean;
    ln2o[(size_t)t * CDIM + c] = (v - mean) * rsqrtf(var + 1e-5f) * g[c] + b[c];
}

// ---------------- launch ----------------
extern "C" void kernel_launch(void* const* d_in, const int* in_sizes, int n_in,
                              void* d_out, int out_size) {
    (void)in_sizes; (void)n_in; (void)out_size;
    const float* x       = (const float*)d_in[0];
    const float* mask    = (const float*)d_in[1];
    const int*   relidx  = (const int*)  d_in[2];
    const float* table   = (const float*)d_in[3];
    const float* n1g     = (const float*)d_in[4];
    const float* n1b     = (const float*)d_in[5];
    const float* qkv_w   = (const float*)d_in[6];
    const float* qkv_b   = (const float*)d_in[7];
    const float* proj_w  = (const float*)d_in[8];
    const float* proj_b  = (const float*)d_in[9];
    const float* n2g     = (const float*)d_in[10];
    const float* n2b     = (const float*)d_in[11];
    const float* fc1_w   = (const float*)d_in[12];
    const float* fc1_b   = (const float*)d_in[13];
    const float* fc2_w   = (const float*)d_in[14];
    const float* fc2_b   = (const float*)d_in[15];
    float* out = (float*)d_out;

    float *xw, *qkvb, *bias6, *attn, *proj, *xres, *ln2, *h1;
    cudaGetSymbolAddress((void**)&xw,    g_xw);
    cudaGetSymbolAddress((void**)&qkvb,  g_qkv);
    cudaGetSymbolAddress((void**)&bias6, g_bias6);
    cudaGetSymbolAddress((void**)&attn,  g_attn);
    cudaGetSymbolAddress((void**)&proj,  g_proj);
    cudaGetSymbolAddress((void**)&xres,  g_xres);
    cudaGetSymbolAddress((void**)&ln2,   g_ln2);
    cudaGetSymbolAddress((void**)&h1,    g_h1);

    static const size_t ATTN_SMEM = (size_t)(NTOK * 33 * 2 + NTOK + 32 + 256) * sizeof(float);
    cudaFuncSetAttribute(attn_kernel, cudaFuncAttributeMaxDynamicSharedMemorySize, (int)ATTN_SMEM);

    // 1. rel-position bias expansion
    bias_pre_kernel<<<(NN + 255) / 256, 256>>>(relidx, table, bias6);
    // 2. LN1 + shift + partition
    ln1_kernel<<<TOK, CDIM>>>(x, n1g, n1b, xw);
    // 3. QKV GEMM: (43904,192) x (576,192)^T
    gemm_nt_kernel<<<dim3(576 / 64, TOK / 64), 256>>>(xw, qkv_w, qkv_b, nullptr, qkvb,
                                                      TOK, 3 * CDIM, CDIM, 0);
    // 4. attention
    attn_kernel<<<TOTWIN * HEADS, 256, ATTN_SMEM>>>(qkvb, bias6, mask, attn);
    // 5. proj GEMM
    gemm_nt_kernel<<<dim3(CDIM / 64, TOK / 64), 256>>>(attn, proj_w, proj_b, nullptr, proj,
                                                       TOK, CDIM, CDIM, 0);
    // 6. reverse + residual + LN2
    ln2res_kernel<<<TOK, CDIM>>>(x, proj, n2g, n2b, xres, ln2);
    // 7. FC1 + exact GELU
    gemm_nt_kernel<<<dim3(HID / 64, TOK / 64), 256>>>(ln2, fc1_w, fc1_b, nullptr, h1,
                                                      TOK, HID, CDIM, 1);
    // 8. FC2 + residual -> out
    gemm_nt_kernel<<<dim3(CDIM / 64, TOK / 64), 256>>>(h1, fc2_w, fc2_b, xres, out,
                                                       TOK, CDIM, HID, 2);
}

// round 3
// speedup vs baseline: 1.5868x; 1.5868x over previous
#include <cuda_runtime.h>
#include <cuda_bf16.h>
#include <math.h>
#include <stdint.h>

// ---------------- problem constants ----------------
#define BATCH   2
#define DSZ     28
#define WS      7
#define SHIFT_  3
#define CDIM    192
#define HEADS   6
#define HD      32
#define NTOK    343
#define NWIN    64
#define TOTWIN  128
#define TOK     43904
#define HID     768
#define NN      117649
#define SCALE   0.17677669529663687f

// GEMM tiling
#define BM      128
#define BN      64
#define KB      64

// ---------------- scratch (device globals) ----------------
__device__ __nv_bfloat16 g_xwb [TOK * CDIM];
__device__ float         g_qkv [TOK * 3 * CDIM];
__device__ float         g_bias6[HEADS * NN];
__device__ __nv_bfloat16 g_attnb[TOK * CDIM];
__device__ float         g_proj[TOK * CDIM];
__device__ float         g_xres[TOK * CDIM];
__device__ __nv_bfloat16 g_ln2b[TOK * CDIM];
__device__ __nv_bfloat16 g_h1b [TOK * HID];
__device__ __nv_bfloat16 g_wqkv[3 * CDIM * CDIM];
__device__ __nv_bfloat16 g_wproj[CDIM * CDIM];
__device__ __nv_bfloat16 g_wfc1[HID * CDIM];
__device__ __nv_bfloat16 g_wfc2[CDIM * HID];

// ---------------- helpers ----------------
__device__ __forceinline__ uint32_t s2u(const void* p) {
    uint32_t r;
    asm("{ .reg .u64 t; cvta.to.shared.u64 t, %1; cvt.u32.u64 %0, t; }" : "=r"(r) : "l"(p));
    return r;
}
__device__ __forceinline__ float warpSum(float v) {
#pragma unroll
    for (int o = 16; o; o >>= 1) v += __shfl_xor_sync(0xffffffffu, v, o);
    return v;
}
__device__ __forceinline__ float warpMax(float v) {
#pragma unroll
    for (int o = 16; o; o >>= 1) v = fmaxf(v, __shfl_xor_sync(0xffffffffu, v, o));
    return v;
}
__device__ __forceinline__ int token_to_winrow(int t) {
    int b   = t / (DSZ * DSZ * DSZ);
    int rem = t - b * (DSZ * DSZ * DSZ);
    int dd  = rem / (DSZ * DSZ);
    int hh  = (rem / DSZ) % DSZ;
    int ww  = rem % DSZ;
    int i = (dd + DSZ - SHIFT_) % DSZ;
    int j = (hh + DSZ - SHIFT_) % DSZ;
    int k = (ww + DSZ - SHIFT_) % DSZ;
    int win = (i / WS) * 16 + (j / WS) * 4 + (k / WS);
    int n   = (i % WS) * 49 + (j % WS) * 7 + (k % WS);
    return (b * NWIN + win) * NTOK + n;
}

// ---------------- small kernels ----------------
__global__ void cvt_kernel(const float* __restrict__ a, __nv_bfloat16* __restrict__ b, int n) {
    int i = blockIdx.x * 256 + threadIdx.x;
    if (i < n) b[i] = __float2bfloat16(a[i]);
}

__global__ void bias_pre_kernel(const int* __restrict__ rel_index,
                                const float* __restrict__ table,
                                float* __restrict__ bias6) {
    int ij = blockIdx.x * 256 + threadIdx.x;
    if (ij >= NN) return;
    int r = rel_index[ij];
#pragma unroll
    for (int h = 0; h < HEADS; h++)
        bias6[h * NN + ij] = table[r * HEADS + h];
}

__global__ __launch_bounds__(CDIM) void ln1_kernel(const float* __restrict__ x,
                                                   const float* __restrict__ g,
                                                   const float* __restrict__ b,
                                                   __nv_bfloat16* __restrict__ xw) {
    __shared__ float red[12];
    int t = blockIdx.x;
    int c = threadIdx.x;
    float v = x[(size_t)t * CDIM + c];
    float s  = warpSum(v);
    float s2 = warpSum(v * v);
    int w = c >> 5;
    if ((c & 31) == 0) { red[w] = s; red[6 + w] = s2; }
    __syncthreads();
    float ts = 0.f, ts2 = 0.f;
#pragma unroll
    for (int i = 0; i < 6; i++) { ts += red[i]; ts2 += red[6 + i]; }
    float mean = ts * (1.0f / CDIM);
    float var  = ts2 * (1.0f / CDIM) - mean * mean;
    float o = (v - mean) * rsqrtf(var + 1e-5f) * g[c] + b[c];
    int row = token_to_winrow(t);
    xw[(size_t)row * CDIM + c] = __float2bfloat16(o);
}

// ---------------- HMMA bf16 GEMM: C = A @ W^T (+bias, epilogue) ----------------
// A: (M,Ktot) bf16 row-major; W: (Ntot,Ktot) bf16 row-major (NT).
// EPI: 0 = bias -> fp32; 1 = bias+gelu -> bf16; 2 = bias+resid -> fp32
template <int EPI>
__global__ __launch_bounds__(256)
void gemm_mma_kernel(const __nv_bfloat16* __restrict__ A,
                     const __nv_bfloat16* __restrict__ Wt,
                     const float* __restrict__ bias,
                     const float* __restrict__ resid,
                     void* __restrict__ Cv, int Ktot, int Ntot)
{
    __shared__ __align__(1024) char smA[BM * KB * 2];   // 16KB, 128B rows, SW128 swizzle
    __shared__ __align__(1024) char smB[BN * KB * 2];   // 8KB
    const uint32_t sA = s2u(smA);
    const uint32_t sB = s2u(smB);
    const int tid = threadIdx.x;
    const int lane = tid & 31;
    const int wid = tid >> 5;
    const int wm = (wid & 3) * 32;     // warp m offset within tile
    const int wn = (wid >> 2) * 32;    // warp n offset within tile
    const int bm = blockIdx.y * BM;
    const int bn = blockIdx.x * BN;

    float acc[2][4][4];
#pragma unroll
    for (int a = 0; a < 2; a++)
#pragma unroll
        for (int b = 0; b < 4; b++)
#pragma unroll
            for (int c = 0; c < 4; c++) acc[a][b][c] = 0.f;

    // per-thread staged-load coords: 8 bf16 (16B) per op
    const int lr = tid >> 3;            // 0..31 (row group stride 32/ A) ; for B rows 0..31
    const int lc8 = (tid & 7) * 8;      // col in bf16 units: 0..56

    for (int k0 = 0; k0 < Ktot; k0 += KB) {
        // A tile: 128 rows x 64 cols
#pragma unroll
        for (int rr = 0; rr < 4; rr++) {
            int r = lr + rr * 32;
            uint4 v = *(const uint4*)(A + (size_t)(bm + r) * Ktot + k0 + lc8);
            uint32_t off = (uint32_t)(r * 128 + lc8 * 2);
            off ^= (off >> 3) & 0x70;
            *(uint4*)(smA + off) = v;
        }
        // B tile: 64 rows x 64 cols
        {
            int r = lr + ((tid & 256) ? 0 : 0);  // lr 0..31, need 64 rows: 2 passes
#pragma unroll
            for (int rr = 0; rr < 2; rr++) {
                int br = lr + rr * 32;
                uint4 v = *(const uint4*)(Wt + (size_t)(bn + br) * Ktot + k0 + lc8);
                uint32_t off = (uint32_t)(br * 128 + lc8 * 2);
                off ^= (off >> 3) & 0x70;
                *(uint4*)(smB + off) = v;
            }
            (void)r;
        }
        __syncthreads();

#pragma unroll
        for (int ks = 0; ks < KB / 16; ks++) {
            uint32_t a0[2], a1[2], a2[2], a3[2];
            uint32_t bfr[4];
            // A fragments: two m16 tiles
#pragma unroll
            for (int mi = 0; mi < 2; mi++) {
                uint32_t off = (uint32_t)((wm + mi * 16 + (lane & 15)) * 128 + ks * 32 + (lane >> 4) * 16);
                off ^= (off >> 3) & 0x70;
                uint32_t r0, r1, r2, r3;
                asm volatile("ldmatrix.sync.aligned.m8n8.x4.shared.b16 {%0,%1,%2,%3}, [%4];"
                             : "=r"(r0), "=r"(r1), "=r"(r2), "=r"(r3) : "r"(sA + off));
                a0[mi] = r0; a1[mi] = r1; a2[mi] = r2; a3[mi] = r3;
            }
            // B fragments: 4 n8 tiles via 2 x4 loads (each covers n16 x k16)
#pragma unroll
            for (int nj = 0; nj < 2; nj++) {
                uint32_t off = (uint32_t)((wn + nj * 16 + (lane & 15)) * 128 + ks * 32 + (lane >> 4) * 16);
                off ^= (off >> 3) & 0x70;
                uint32_t r0, r1, r2, r3;
                asm volatile("ldmatrix.sync.aligned.m8n8.x4.shared.b16 {%0,%1,%2,%3}, [%4];"
                             : "=r"(r0), "=r"(r1), "=r"(r2), "=r"(r3) : "r"(sB + off));
                // tile (2*nj):   {r0, r2}   tile (2*nj+1): {r1, r3}
#pragma unroll
                for (int mi = 0; mi < 2; mi++) {
                    asm volatile(
                        "mma.sync.aligned.m16n8k16.row.col.f32.bf16.bf16.f32 "
                        "{%0,%1,%2,%3}, {%4,%5,%6,%7}, {%8,%9}, {%0,%1,%2,%3};"
                        : "+f"(acc[mi][2 * nj][0]), "+f"(acc[mi][2 * nj][1]),
                          "+f"(acc[mi][2 * nj][2]), "+f"(acc[mi][2 * nj][3])
                        : "r"(a0[mi]), "r"(a1[mi]), "r"(a2[mi]), "r"(a3[mi]),
                          "r"(r0), "r"(r2));
                    asm volatile(
                        "mma.sync.aligned.m16n8k16.row.col.f32.bf16.bf16.f32 "
                        "{%0,%1,%2,%3}, {%4,%5,%6,%7}, {%8,%9}, {%0,%1,%2,%3};"
                        : "+f"(acc[mi][2 * nj + 1][0]), "+f"(acc[mi][2 * nj + 1][1]),
                          "+f"(acc[mi][2 * nj + 1][2]), "+f"(acc[mi][2 * nj + 1][3])
                        : "r"(a0[mi]), "r"(a1[mi]), "r"(a2[mi]), "r"(a3[mi]),
                          "r"(r1), "r"(r3));
                }
            }
            (void)bfr;
        }
        __syncthreads();
    }

    // epilogue: direct global stores (float2 / bf16x2 pairs)
    const int gq = lane >> 2;       // 0..7 row-in-8
    const int tg = lane & 3;        // col pair index
#pragma unroll
    for (int mi = 0; mi < 2; mi++) {
#pragma unroll
        for (int ni = 0; ni < 4; ni++) {
            int col = bn + wn + ni * 8 + tg * 2;
            float bia0 = bias[col], bia1 = bias[col + 1];
#pragma unroll
            for (int half = 0; half < 2; half++) {
                int row = bm + wm + mi * 16 + gq + half * 8;
                float v0 = acc[mi][ni][half * 2 + 0] + bia0;
                float v1 = acc[mi][ni][half * 2 + 1] + bia1;
                size_t oi = (size_t)row * Ntot + col;
                if (EPI == 1) {
                    v0 = 0.5f * v0 * (1.0f + erff(v0 * 0.7071067811865476f));
                    v1 = 0.5f * v1 * (1.0f + erff(v1 * 0.7071067811865476f));
                    __nv_bfloat162 p;
                    p.x = __float2bfloat16(v0); p.y = __float2bfloat16(v1);
                    *(__nv_bfloat162*)((__nv_bfloat16*)Cv + oi) = p;
                } else if (EPI == 2) {
                    float2 rv = *(const float2*)(resid + oi);
                    float2 o; o.x = v0 + rv.x; o.y = v1 + rv.y;
                    *(float2*)((float*)Cv + oi) = o;
                } else {
                    float2 o; o.x = v0; o.y = v1;
                    *(float2*)((float*)Cv + oi) = o;
                }
            }
        }
    }
}

// ---------------- attention (grid (768, 4): row splits) ----------------
__global__ __launch_bounds__(256) void attn_kernel(
    const float* __restrict__ qkv, const float* __restrict__ bias6,
    const float* __restrict__ mask, __nv_bfloat16* __restrict__ out)
{
    extern __shared__ float sm[];
    float* ks   = sm;
    float* vs   = ks + NTOK * 33;
    float* sc   = vs + NTOK * 33;
    float* qrow = sc + NTOK;
    float* part = qrow + 32;
    __shared__ float red[8];

    const int bx  = blockIdx.x;
    const int w   = bx / HEADS;
    const int h   = bx - w * HEADS;
    const int mw  = w % NWIN;
    const int tid = threadIdx.x;
    const int i0  = blockIdx.y * 86;
    int i1 = i0 + 86; if (i1 > NTOK) i1 = NTOK;

    const float* base = qkv + (size_t)w * NTOK * (3 * CDIM) + h * HD;
    for (int idx = tid; idx < NTOK * HD; idx += 256) {
        int j = idx >> 5, d = idx & 31;
        const float* rowp = base + (size_t)j * (3 * CDIM);
        ks[j * 33 + d] = rowp[CDIM + d];
        vs[j * 33 + d] = rowp[2 * CDIM + d];
    }
    __syncthreads();

    const float* biasrow0 = bias6 + (size_t)h * NN;
    const float* maskrow0 = mask + (size_t)mw * NN;

    for (int i = i0; i < i1; i++) {
        if (tid < 32) qrow[tid] = base[(size_t)i * (3 * CDIM) + tid];
        __syncthreads();

        float lmax = -1e30f;
        const float* brow = biasrow0 + (size_t)i * NTOK;
        const float* mrow = maskrow0 + (size_t)i * NTOK;
        for (int j = tid; j < NTOK; j += 256) {
            float s = 0.f;
            const float* kj = ks + j * 33;
#pragma unroll
            for (int d = 0; d < HD; d++) s += qrow[d] * kj[d];
            s = s * SCALE + brow[j] + mrow[j];
            sc[j] = s;
            lmax = fmaxf(lmax, s);
        }
        {
            float wv = warpMax(lmax);
            if ((tid & 31) == 0) red[tid >> 5] = wv;
            __syncthreads();
            lmax = red[0];
#pragma unroll
            for (int r = 1; r < 8; r++) lmax = fmaxf(lmax, red[r]);
        }
        __syncthreads();
        float lsum = 0.f;
        for (int j = tid; j < NTOK; j += 256) {
            float e = __expf(sc[j] - lmax);
            sc[j] = e;
            lsum += e;
        }
        {
            float wv = warpSum(lsum);
            if ((tid & 31) == 0) red[tid >> 5] = wv;
            __syncthreads();
            lsum = 0.f;
#pragma unroll
            for (int r = 0; r < 8; r++) lsum += red[r];
        }
        __syncthreads();
        float inv = __frcp_rn(lsum);

        {
            int d = tid & 31, c = tid >> 5;
            int j0 = c * 43;
            int j1 = j0 + 43; if (j1 > NTOK) j1 = NTOK;
            float p = 0.f;
            for (int j = j0; j < j1; j++) p += sc[j] * vs[j * 33 + d];
            part[c * 32 + d] = p;
        }
        __syncthreads();
        if (tid < 32) {
            float o = 0.f;
#pragma unroll
            for (int c = 0; c < 8; c++) o += part[c * 32 + tid];
            out[((size_t)w * NTOK + i) * CDIM + h * HD + tid] = __float2bfloat16(o * inv);
        }
        __syncthreads();
    }
}

// ---------------- reverse + residual + LN2 ----------------
__global__ __launch_bounds__(CDIM) void ln2res_kernel(const float* __restrict__ x,
                                                      const float* __restrict__ proj,
                                                      const float* __restrict__ g,
                                                      const float* __restrict__ b,
                                                      float* __restrict__ xres,
                                                      __nv_bfloat16* __restrict__ ln2o) {
    __shared__ float red[12];
    int t = blockIdx.x;
    int c = threadIdx.x;
    int row = token_to_winrow(t);
    float v = x[(size_t)t * CDIM + c] + proj[(size_t)row * CDIM + c];
    xres[(size_t)t * CDIM + c] = v;

    float s  = warpSum(v);
    float s2 = warpSum(v * v);
    int w = c >> 5;
    if ((c & 31) == 0) { red[w] = s; red[6 + w] = s2; }
    __syncthreads();
    float ts = 0.f, ts2 = 0.f;
#pragma unroll
    for (int i = 0; i < 6; i++) { ts += red[i]; ts2 += red[6 + i]; }
    float mean = ts * (1.0f / CDIM);
    float var  = ts2 * (1.0f / CDIM) - mean * mean;
    ln2o[(size_t)t * CDIM + c] = __float2bfloat16((v - mean) * rsqrtf(var + 1e-5f) * g[c] + b[c]);
}

// ---------------- launch ----------------
extern "C" void kernel_launch(void* const* d_in, const int* in_sizes, int n_in,
                              void* d_out, int out_size) {
    (void)in_sizes; (void)n_in; (void)out_size;
    const float* x       = (const float*)d_in[0];
    const float* mask    = (const float*)d_in[1];
    const int*   relidx  = (const int*)  d_in[2];
    const float* table   = (const float*)d_in[3];
    const float* n1g     = (const float*)d_in[4];
    const float* n1b     = (const float*)d_in[5];
    const float* qkv_w   = (const float*)d_in[6];
    const float* qkv_b   = (const float*)d_in[7];
    const float* proj_w  = (const float*)d_in[8];
    const float* proj_b  = (const float*)d_in[9];
    const float* n2g     = (const float*)d_in[10];
    const float* n2b     = (const float*)d_in[11];
    const float* fc1_w   = (const float*)d_in[12];
    const float* fc1_b   = (const float*)d_in[13];
    const float* fc2_w   = (const float*)d_in[14];
    const float* fc2_b   = (const float*)d_in[15];
    float* out = (float*)d_out;

    __nv_bfloat16 *xwb, *attnb, *ln2b, *h1b, *wqkv, *wproj, *wfc1, *wfc2;
    float *qkvb, *bias6, *proj, *xres;
    cudaGetSymbolAddress((void**)&xwb,   g_xwb);
    cudaGetSymbolAddress((void**)&qkvb,  g_qkv);
    cudaGetSymbolAddress((void**)&bias6, g_bias6);
    cudaGetSymbolAddress((void**)&attnb, g_attnb);
    cudaGetSymbolAddress((void**)&proj,  g_proj);
    cudaGetSymbolAddress((void**)&xres,  g_xres);
    cudaGetSymbolAddress((void**)&ln2b,  g_ln2b);
    cudaGetSymbolAddress((void**)&h1b,   g_h1b);
    cudaGetSymbolAddress((void**)&wqkv,  g_wqkv);
    cudaGetSymbolAddress((void**)&wproj, g_wproj);
    cudaGetSymbolAddress((void**)&wfc1,  g_wfc1);
    cudaGetSymbolAddress((void**)&wfc2,  g_wfc2);

    static const size_t ATTN_SMEM = (size_t)(NTOK * 33 * 2 + NTOK + 32 + 256) * sizeof(float);
    cudaFuncSetAttribute(attn_kernel, cudaFuncAttributeMaxDynamicSharedMemorySize, (int)ATTN_SMEM);

    cvt_kernel<<<(3 * CDIM * CDIM + 255) / 256, 256>>>(qkv_w, wqkv, 3 * CDIM * CDIM);
    cvt_kernel<<<(CDIM * CDIM + 255) / 256, 256>>>(proj_w, wproj, CDIM * CDIM);
    cvt_kernel<<<(HID * CDIM + 255) / 256, 256>>>(fc1_w, wfc1, HID * CDIM);
    cvt_kernel<<<(CDIM * HID + 255) / 256, 256>>>(fc2_w, wfc2, CDIM * HID);

    bias_pre_kernel<<<(NN + 255) / 256, 256>>>(relidx, table, bias6);
    ln1_kernel<<<TOK, CDIM>>>(x, n1g, n1b, xwb);
    // QKV: (43904 x 576 x 192)
    gemm_mma_kernel<0><<<dim3(576 / BN, TOK / BM), 256>>>(xwb, wqkv, qkv_b, nullptr, qkvb, CDIM, 3 * CDIM);
    attn_kernel<<<dim3(TOTWIN * HEADS, 4), 256, ATTN_SMEM>>>(qkvb, bias6, mask, attnb);
    // proj: (43904 x 192 x 192)
    gemm_mma_kernel<0><<<dim3(CDIM / BN, TOK / BM), 256>>>(attnb, wproj, proj_b, nullptr, proj, CDIM, CDIM);
    ln2res_kernel<<<TOK, CDIM>>>(x, proj, n2g, n2b, xres, ln2b);
    // FC1 + GELU: (43904 x 768 x 192) -> bf16
    gemm_mma_kernel<1><<<dim3(HID / BN, TOK / BM), 256>>>(ln2b, wfc1, fc1_b, nullptr, h1b, CDIM, HID);
    // FC2 + residual: (43904 x 192 x 768) -> fp32 out
    gemm_mma_kernel<2><<<dim3(CDIM / BN, TOK / BM), 256>>>(h1b, wfc2, fc2_b, xres, out, HID, CDIM);
}

// round 4
// speedup vs baseline: 6.1826x; 3.8963x over previous
#include <cuda_runtime.h>
#include <cuda_bf16.h>
#include <math.h>
#include <stdint.h>

// ---------------- problem constants ----------------
#define BATCH   2
#define DSZ     28
#define WS      7
#define SHIFT_  3
#define CDIM    192
#define HEADS   6
#define HD      32
#define NTOK    343
#define NWIN    64
#define TOTWIN  128
#define TOK     43904
#define HID     768
#define NN      117649
#define SCALE   0.17677669529663687f

// GEMM tiling
#define BM      128
#define BN      64
#define KB      64

// attention tiling
#define QT      64
#define NC      64
#define KPAD    384
#define NCH     6
#define QPITCH  80
#define KPITCH  80
#define VPITCH  784
#define PPITCH  144
// smem offsets (bytes)
#define AOFF_K  0
#define AOFF_V  30720
#define AOFF_Q  55808
#define AOFF_P  60928
#define AOFF_RS 70144
#define ATTN_SMEM_BYTES 70656

// ---------------- scratch (device globals) ----------------
__device__ __nv_bfloat16 g_xwb [TOK * CDIM];
__device__ __nv_bfloat16 g_qkvb[TOK * 3 * CDIM];
__device__ float         g_bias6[HEADS * NN];
__device__ __nv_bfloat16 g_attnb[TOK * CDIM];
__device__ float         g_proj[TOK * CDIM];
__device__ float         g_xres[TOK * CDIM];
__device__ __nv_bfloat16 g_ln2b[TOK * CDIM];
__device__ __nv_bfloat16 g_h1b [TOK * HID];
__device__ __nv_bfloat16 g_wqkv[3 * CDIM * CDIM];
__device__ __nv_bfloat16 g_wproj[CDIM * CDIM];
__device__ __nv_bfloat16 g_wfc1[HID * CDIM];
__device__ __nv_bfloat16 g_wfc2[CDIM * HID];

// ---------------- helpers ----------------
__device__ __forceinline__ uint32_t s2u(const void* p) {
    uint32_t r;
    asm("{ .reg .u64 t; cvta.to.shared.u64 t, %1; cvt.u32.u64 %0, t; }" : "=r"(r) : "l"(p));
    return r;
}
__device__ __forceinline__ float warpSum(float v) {
#pragma unroll
    for (int o = 16; o; o >>= 1) v += __shfl_xor_sync(0xffffffffu, v, o);
    return v;
}
__device__ __forceinline__ int token_to_winrow(int t) {
    int b   = t / (DSZ * DSZ * DSZ);
    int rem = t - b * (DSZ * DSZ * DSZ);
    int dd  = rem / (DSZ * DSZ);
    int hh  = (rem / DSZ) % DSZ;
    int ww  = rem % DSZ;
    int i = (dd + DSZ - SHIFT_) % DSZ;
    int j = (hh + DSZ - SHIFT_) % DSZ;
    int k = (ww + DSZ - SHIFT_) % DSZ;
    int win = (i / WS) * 16 + (j / WS) * 4 + (k / WS);
    int n   = (i % WS) * 49 + (j % WS) * 7 + (k % WS);
    return (b * NWIN + win) * NTOK + n;
}

#define CP_ASYNC16(dst_u32, src_ptr) \
    asm volatile("cp.async.cg.shared.global [%0], [%1], 16;" :: "r"(dst_u32), "l"(src_ptr))
#define CP_COMMIT() asm volatile("cp.async.commit_group;")
#define CP_WAIT(n)  asm volatile("cp.async.wait_group %0;" :: "n"(n))

#define LDMX4(r0, r1, r2, r3, addr) \
    asm volatile("ldmatrix.sync.aligned.m8n8.x4.shared.b16 {%0,%1,%2,%3}, [%4];" \
                 : "=r"(r0), "=r"(r1), "=r"(r2), "=r"(r3) : "r"(addr))

#define MMA16816(d, a0, a1, a2, a3, b0, b1) \
    asm volatile("mma.sync.aligned.m16n8k16.row.col.f32.bf16.bf16.f32 " \
                 "{%0,%1,%2,%3}, {%4,%5,%6,%7}, {%8,%9}, {%0,%1,%2,%3};" \
                 : "+f"((d)[0]), "+f"((d)[1]), "+f"((d)[2]), "+f"((d)[3]) \
                 : "r"(a0), "r"(a1), "r"(a2), "r"(a3), "r"(b0), "r"(b1))

// ---------------- small kernels ----------------
__global__ void cvt_kernel(const float* __restrict__ a, __nv_bfloat16* __restrict__ b, int n) {
    int i = blockIdx.x * 256 + threadIdx.x;
    if (i < n) b[i] = __float2bfloat16(a[i]);
}

__global__ void bias_pre_kernel(const int* __restrict__ rel_index,
                                const float* __restrict__ table,
                                float* __restrict__ bias6) {
    int ij = blockIdx.x * 256 + threadIdx.x;
    if (ij >= NN) return;
    int r = rel_index[ij];
#pragma unroll
    for (int h = 0; h < HEADS; h++)
        bias6[h * NN + ij] = table[r * HEADS + h];
}

__global__ __launch_bounds__(CDIM) void ln1_kernel(const float* __restrict__ x,
                                                   const float* __restrict__ g,
                                                   const float* __restrict__ b,
                                                   __nv_bfloat16* __restrict__ xw) {
    __shared__ float red[12];
    int t = blockIdx.x;
    int c = threadIdx.x;
    float v = x[(size_t)t * CDIM + c];
    float s  = warpSum(v);
    float s2 = warpSum(v * v);
    int w = c >> 5;
    if ((c & 31) == 0) { red[w] = s; red[6 + w] = s2; }
    __syncthreads();
    float ts = 0.f, ts2 = 0.f;
#pragma unroll
    for (int i = 0; i < 6; i++) { ts += red[i]; ts2 += red[6 + i]; }
    float mean = ts * (1.0f / CDIM);
    float var  = ts2 * (1.0f / CDIM) - mean * mean;
    float o = (v - mean) * rsqrtf(var + 1e-5f) * g[c] + b[c];
    int row = token_to_winrow(t);
    xw[(size_t)row * CDIM + c] = __float2bfloat16(o);
}

// ---------------- HMMA bf16 GEMM, 2-stage cp.async pipeline ----------------
// C = A @ W^T (+bias); A (M,Ktot) bf16, W (Ntot,Ktot) bf16.
// EPI: 0 = bias -> fp32; 1 = bias+gelu -> bf16; 2 = bias+resid -> fp32; 3 = bias -> bf16
template <int EPI>
__global__ __launch_bounds__(256)
void gemm_mma_kernel(const __nv_bfloat16* __restrict__ A,
                     const __nv_bfloat16* __restrict__ Wt,
                     const float* __restrict__ bias,
                     const float* __restrict__ resid,
                     void* __restrict__ Cv, int Ktot, int Ntot)
{
    __shared__ __align__(1024) char smA[2][BM * KB * 2];
    __shared__ __align__(1024) char smB[2][BN * KB * 2];
    const int tid = threadIdx.x;
    const int lane = tid & 31;
    const int wid = tid >> 5;
    const int wm = (wid & 3) * 32;
    const int wn = (wid >> 2) * 32;
    const int bm = blockIdx.y * BM;
    const int bn = blockIdx.x * BN;

    float acc[2][4][4];
#pragma unroll
    for (int a = 0; a < 2; a++)
#pragma unroll
        for (int b = 0; b < 4; b++)
#pragma unroll
            for (int c = 0; c < 4; c++) acc[a][b][c] = 0.f;

    const int lr = tid >> 3;
    const int lc8 = (tid & 7) * 8;

    const int nch = Ktot / KB;

    // prologue: stage 0
    {
        const int k0 = 0;
#pragma unroll
        for (int rr = 0; rr < 4; rr++) {
            int r = lr + rr * 32;
            uint32_t off = (uint32_t)(r * 128 + lc8 * 2);
            off ^= (off >> 3) & 0x70;
            CP_ASYNC16(s2u(smA[0] + off), A + (size_t)(bm + r) * Ktot + k0 + lc8);
        }
#pragma unroll
        for (int rr = 0; rr < 2; rr++) {
            int br = lr + rr * 32;
            uint32_t off = (uint32_t)(br * 128 + lc8 * 2);
            off ^= (off >> 3) & 0x70;
            CP_ASYNC16(s2u(smB[0] + off), Wt + (size_t)(bn + br) * Ktot + k0 + lc8);
        }
        CP_COMMIT();
    }

    for (int ch = 0; ch < nch; ch++) {
        const int cur = ch & 1;
        if (ch + 1 < nch) {
            const int k0 = (ch + 1) * KB;
            const int nxt = cur ^ 1;
#pragma unroll
            for (int rr = 0; rr < 4; rr++) {
                int r = lr + rr * 32;
                uint32_t off = (uint32_t)(r * 128 + lc8 * 2);
                off ^= (off >> 3) & 0x70;
                CP_ASYNC16(s2u(smA[nxt] + off), A + (size_t)(bm + r) * Ktot + k0 + lc8);
            }
#pragma unroll
            for (int rr = 0; rr < 2; rr++) {
                int br = lr + rr * 32;
                uint32_t off = (uint32_t)(br * 128 + lc8 * 2);
                off ^= (off >> 3) & 0x70;
                CP_ASYNC16(s2u(smB[nxt] + off), Wt + (size_t)(bn + br) * Ktot + k0 + lc8);
            }
            CP_COMMIT();
            CP_WAIT(1);
        } else {
            CP_WAIT(0);
        }
        __syncthreads();

        const uint32_t sA = s2u(smA[cur]);
        const uint32_t sB = s2u(smB[cur]);
#pragma unroll
        for (int ks = 0; ks < KB / 16; ks++) {
            uint32_t a0[2], a1[2], a2[2], a3[2];
#pragma unroll
            for (int mi = 0; mi < 2; mi++) {
                uint32_t off = (uint32_t)((wm + mi * 16 + (lane & 15)) * 128 + ks * 32 + (lane >> 4) * 16);
                off ^= (off >> 3) & 0x70;
                LDMX4(a0[mi], a1[mi], a2[mi], a3[mi], sA + off);
            }
#pragma unroll
            for (int nj = 0; nj < 2; nj++) {
                uint32_t off = (uint32_t)((wn + nj * 16 + (lane & 15)) * 128 + ks * 32 + (lane >> 4) * 16);
                off ^= (off >> 3) & 0x70;
                uint32_t r0, r1, r2, r3;
                LDMX4(r0, r1, r2, r3, sB + off);
#pragma unroll
                for (int mi = 0; mi < 2; mi++) {
                    MMA16816(acc[mi][2 * nj], a0[mi], a1[mi], a2[mi], a3[mi], r0, r2);
                    MMA16816(acc[mi][2 * nj + 1], a0[mi], a1[mi], a2[mi], a3[mi], r1, r3);
                }
            }
        }
        __syncthreads();
    }

    const int gq = lane >> 2;
    const int tg = lane & 3;
#pragma unroll
    for (int mi = 0; mi < 2; mi++) {
#pragma unroll
        for (int ni = 0; ni < 4; ni++) {
            int col = bn + wn + ni * 8 + tg * 2;
            float bia0 = bias[col], bia1 = bias[col + 1];
#pragma unroll
            for (int half = 0; half < 2; half++) {
                int row = bm + wm + mi * 16 + gq + half * 8;
                float v0 = acc[mi][ni][half * 2 + 0] + bia0;
                float v1 = acc[mi][ni][half * 2 + 1] + bia1;
                size_t oi = (size_t)row * Ntot + col;
                if (EPI == 1) {
                    v0 = 0.5f * v0 * (1.0f + erff(v0 * 0.7071067811865476f));
                    v1 = 0.5f * v1 * (1.0f + erff(v1 * 0.7071067811865476f));
                    __nv_bfloat162 p;
                    p.x = __float2bfloat16(v0); p.y = __float2bfloat16(v1);
                    *(__nv_bfloat162*)((__nv_bfloat16*)Cv + oi) = p;
                } else if (EPI == 2) {
                    float2 rv = *(const float2*)(resid + oi);
                    float2 o; o.x = v0 + rv.x; o.y = v1 + rv.y;
                    *(float2*)((float*)Cv + oi) = o;
                } else if (EPI == 3) {
                    __nv_bfloat162 p;
                    p.x = __float2bfloat16(v0); p.y = __float2bfloat16(v1);
                    *(__nv_bfloat162*)((__nv_bfloat16*)Cv + oi) = p;
                } else {
                    float2 o; o.x = v0; o.y = v1;
                    *(float2*)((float*)Cv + oi) = o;
                }
            }
        }
    }
}

// ---------------- tensor-core attention ----------------
// grid (TOTWIN*HEADS, 6); block 256. Each block: 64 query rows, all 343 keys.
__global__ __launch_bounds__(256) void attn_tc_kernel(
    const __nv_bfloat16* __restrict__ qkv, const float* __restrict__ bias6,
    const float* __restrict__ mask, __nv_bfloat16* __restrict__ out)
{
    extern __shared__ __align__(1024) char sm[];
    const uint32_t uK = s2u(sm + AOFF_K);
    const uint32_t uV = s2u(sm + AOFF_V);
    const uint32_t uQ = s2u(sm + AOFF_Q);
    const uint32_t uP = s2u(sm + AOFF_P);
    float* rs = (float*)(sm + AOFF_RS);

    const int bx = blockIdx.x;
    const int w  = bx / HEADS;
    const int h  = bx - w * HEADS;
    const int mw = w % NWIN;
    const int q0 = blockIdx.y * QT;
    const int tid = threadIdx.x;
    const int lane = tid & 31;
    const int wid = tid >> 5;

    const __nv_bfloat16* base = qkv + (size_t)w * NTOK * (3 * CDIM);

    // K: 384 rows x 4 x 16B (zero padded)
    for (int idx = tid; idx < KPAD * 4; idx += 256) {
        int j = idx >> 2, s = idx & 3;
        uint4 v = make_uint4(0, 0, 0, 0);
        if (j < NTOK) v = *(const uint4*)(base + (size_t)j * (3 * CDIM) + CDIM + h * HD + s * 8);
        *(uint4*)(sm + AOFF_K + j * KPITCH + s * 16) = v;
    }
    // Q: 64 rows x 4 x 16B
    for (int idx = tid; idx < QT * 4; idx += 256) {
        int r = idx >> 2, s = idx & 3;
        int gq = q0 + r;
        uint4 v = make_uint4(0, 0, 0, 0);
        if (gq < NTOK) v = *(const uint4*)(base + (size_t)gq * (3 * CDIM) + h * HD + s * 8);
        *(uint4*)(sm + AOFF_Q + r * QPITCH + s * 16) = v;
    }
    // V transposed: smV[d][j]
    for (int j = tid; j < KPAD; j += 256) {
        __nv_bfloat16 tmp[32];
        if (j < NTOK) {
            const __nv_bfloat16* vp = base + (size_t)j * (3 * CDIM) + 2 * CDIM + h * HD;
#pragma unroll
            for (int s = 0; s < 4; s++) *(uint4*)(tmp + s * 8) = *(const uint4*)(vp + s * 8);
        } else {
#pragma unroll
            for (int d = 0; d < 32; d++) tmp[d] = __float2bfloat16(0.f);
        }
#pragma unroll
        for (int d = 0; d < 32; d++)
            *(__nv_bfloat16*)(sm + AOFF_V + d * VPITCH + j * 2) = tmp[d];
    }
    __syncthreads();

    // S-mma warp layout: wm in M (4x16), wn in N (2x32)
    const int wm = wid & 3, wn = wid >> 2;
    // PV warp layout: vm in d (2x16), vn in q (4x16)
    const int vm = wid & 1, vn = wid >> 1;
    const int gq_ = lane >> 2, tg = lane & 3;

    float acc_o[2][4];
#pragma unroll
    for (int t = 0; t < 2; t++)
#pragma unroll
        for (int c = 0; c < 4; c++) acc_o[t][c] = 0.f;
    float rs0 = 0.f, rs1 = 0.f;

    const float* brow = bias6 + (size_t)h * NN;
    const float* mrow = mask + (size_t)mw * NN;
    const int r0g = q0 + wm * 16 + gq_;
    const int r1g = r0g + 8;

    for (int ch = 0; ch < NCH; ch++) {
        const int j0 = ch * NC;
        float acc[4][4];
#pragma unroll
        for (int t = 0; t < 4; t++)
#pragma unroll
            for (int c = 0; c < 4; c++) acc[t][c] = 0.f;

        // S = Q @ K^T (64 x 64 chunk)
#pragma unroll
        for (int ks = 0; ks < 2; ks++) {
            uint32_t a0, a1, a2, a3;
            LDMX4(a0, a1, a2, a3,
                  uQ + (uint32_t)((wm * 16 + (lane & 15)) * QPITCH + ks * 32 + (lane >> 4) * 16));
#pragma unroll
            for (int nj = 0; nj < 2; nj++) {
                uint32_t r0, r1, r2, r3;
                LDMX4(r0, r1, r2, r3,
                      uK + (uint32_t)((j0 + wn * 32 + nj * 16 + (lane & 15)) * KPITCH + ks * 32 + (lane >> 4) * 16));
                MMA16816(acc[2 * nj], a0, a1, a2, a3, r0, r2);
                MMA16816(acc[2 * nj + 1], a0, a1, a2, a3, r1, r3);
            }
        }

        // epilogue: exp(scale*s + bias + mask) -> P (bf16), accumulate rowsums
        const bool v0 = (r0g < NTOK);
        const bool v1 = (r1g < NTOK);
        const float* b0p = brow + (size_t)r0g * NTOK;
        const float* m0p = mrow + (size_t)r0g * NTOK;
        const float* b1p = brow + (size_t)r1g * NTOK;
        const float* m1p = mrow + (size_t)r1g * NTOK;
#pragma unroll
        for (int ti = 0; ti < 4; ti++) {
            int jl = wn * 32 + (ti >> 1) * 16 + (ti & 1) * 8 + tg * 2;
            int ja = j0 + jl, jb = ja + 1;
            float e00 = 0.f, e01 = 0.f, e10 = 0.f, e11 = 0.f;
            if (v0 && ja < NTOK) e00 = __expf(fmaf(acc[ti][0], SCALE, b0p[ja] + m0p[ja]));
            if (v0 && jb < NTOK) e01 = __expf(fmaf(acc[ti][1], SCALE, b0p[jb] + m0p[jb]));
            if (v1 && ja < NTOK) e10 = __expf(fmaf(acc[ti][2], SCALE, b1p[ja] + m1p[ja]));
            if (v1 && jb < NTOK) e11 = __expf(fmaf(acc[ti][3], SCALE, b1p[jb] + m1p[jb]));
            rs0 += e00 + e01;
            rs1 += e10 + e11;
            __nv_bfloat162 p0, p1;
            p0.x = __float2bfloat16(e00); p0.y = __float2bfloat16(e01);
            p1.x = __float2bfloat16(e10); p1.y = __float2bfloat16(e11);
            int rloc0 = wm * 16 + gq_;
            *(__nv_bfloat162*)(sm + AOFF_P + rloc0 * PPITCH + jl * 2) = p0;
            *(__nv_bfloat162*)(sm + AOFF_P + (rloc0 + 8) * PPITCH + jl * 2) = p1;
        }
        __syncthreads();

        // O^T += V^T @ P^T  (A = V^T rows d, B = P rows q)
#pragma unroll
        for (int kk = 0; kk < 4; kk++) {
            uint32_t a0, a1, a2, a3;
            LDMX4(a0, a1, a2, a3,
                  uV + (uint32_t)((vm * 16 + (lane & 15)) * VPITCH + j0 * 2 + kk * 32 + (lane >> 4) * 16));
            uint32_t r0, r1, r2, r3;
            LDMX4(r0, r1, r2, r3,
                  uP + (uint32_t)((vn * 16 + (lane & 15)) * PPITCH + kk * 32 + (lane >> 4) * 16));
            MMA16816(acc_o[0], a0, a1, a2, a3, r0, r2);
            MMA16816(acc_o[1], a0, a1, a2, a3, r1, r3);
        }
        __syncthreads();   // P consumed before next chunk overwrites
    }

    // rowsums: reduce over quad (tg), write [row][wn]
    rs0 += __shfl_xor_sync(0xffffffffu, rs0, 1);
    rs0 += __shfl_xor_sync(0xffffffffu, rs0, 2);
    rs1 += __shfl_xor_sync(0xffffffffu, rs1, 1);
    rs1 += __shfl_xor_sync(0xffffffffu, rs1, 2);
    if (tg == 0) {
        rs[(wm * 16 + gq_) * 2 + wn] = rs0;
        rs[(wm * 16 + gq_ + 8) * 2 + wn] = rs1;
    }

    // stage O^T into smem (reuse P region)
    float* Ost = (float*)(sm + AOFF_P);
#pragma unroll
    for (int t = 0; t < 2; t++) {
        int qc = vn * 16 + t * 8 + tg * 2;
        int d0 = vm * 16 + gq_;
        Ost[d0 * 65 + qc]     = acc_o[t][0];
        Ost[d0 * 65 + qc + 1] = acc_o[t][1];
        Ost[(d0 + 8) * 65 + qc]     = acc_o[t][2];
        Ost[(d0 + 8) * 65 + qc + 1] = acc_o[t][3];
    }
    __syncthreads();

    // writeout: thread -> (q = tid/4, 8 d's)
    {
        int q = tid >> 2, ds = (tid & 3) * 8;
        int gq = q0 + q;
        if (gq < NTOK) {
            float inv = __frcp_rn(rs[q * 2] + rs[q * 2 + 1]);
            __nv_bfloat16 o[8];
#pragma unroll
            for (int u = 0; u < 8; u++)
                o[u] = __float2bfloat16(Ost[(ds + u) * 65 + q] * inv);
            *(uint4*)(out + (size_t)(w * NTOK + gq) * CDIM + h * HD + ds) = *(uint4*)o;
        }
    }
}

// ---------------- reverse + residual + LN2 ----------------
__global__ __launch_bounds__(CDIM) void ln2res_kernel(const float* __restrict__ x,
                                                      const float* __restrict__ proj,
                                                      const float* __restrict__ g,
                                                      const float* __restrict__ b,
                                                      float* __restrict__ xres,
                                                      __nv_bfloat16* __restrict__ ln2o) {
    __shared__ float red[12];
    int t = blockIdx.x;
    int c = threadIdx.x;
    int row = token_to_winrow(t);
    float v = x[(size_t)t * CDIM + c] + proj[(size_t)row * CDIM + c];
    xres[(size_t)t * CDIM + c] = v;

    float s  = warpSum(v);
    float s2 = warpSum(v * v);
    int w = c >> 5;
    if ((c & 31) == 0) { red[w] = s; red[6 + w] = s2; }
    __syncthreads();
    float ts = 0.f, ts2 = 0.f;
#pragma unroll
    for (int i = 0; i < 6; i++) { ts += red[i]; ts2 += red[6 + i]; }
    float mean = ts * (1.0f / CDIM);
    float var  = ts2 * (1.0f / CDIM) - mean * mean;
    ln2o[(size_t)t * CDIM + c] = __float2bfloat16((v - mean) * rsqrtf(var + 1e-5f) * g[c] + b[c]);
}

// ---------------- launch ----------------
extern "C" void kernel_launch(void* const* d_in, const int* in_sizes, int n_in,
                              void* d_out, int out_size) {
    (void)in_sizes; (void)n_in; (void)out_size;
    const float* x       = (const float*)d_in[0];
    const float* mask    = (const float*)d_in[1];
    const int*   relidx  = (const int*)  d_in[2];
    const float* table   = (const float*)d_in[3];
    const float* n1g     = (const float*)d_in[4];
    const float* n1b     = (const float*)d_in[5];
    const float* qkv_w   = (const float*)d_in[6];
    const float* qkv_b   = (const float*)d_in[7];
    const float* proj_w  = (const float*)d_in[8];
    const float* proj_b  = (const float*)d_in[9];
    const float* n2g     = (const float*)d_in[10];
    const float* n2b     = (const float*)d_in[11];
    const float* fc1_w   = (const float*)d_in[12];
    const float* fc1_b   = (const float*)d_in[13];
    const float* fc2_w   = (const float*)d_in[14];
    const float* fc2_b   = (const float*)d_in[15];
    float* out = (float*)d_out;

    __nv_bfloat16 *xwb, *qkvb, *attnb, *ln2b, *h1b, *wqkv, *wproj, *wfc1, *wfc2;
    float *bias6, *proj, *xres;
    cudaGetSymbolAddress((void**)&xwb,   g_xwb);
    cudaGetSymbolAddress((void**)&qkvb,  g_qkvb);
    cudaGetSymbolAddress((void**)&bias6, g_bias6);
    cudaGetSymbolAddress((void**)&attnb, g_attnb);
    cudaGetSymbolAddress((void**)&proj,  g_proj);
    cudaGetSymbolAddress((void**)&xres,  g_xres);
    cudaGetSymbolAddress((void**)&ln2b,  g_ln2b);
    cudaGetSymbolAddress((void**)&h1b,   g_h1b);
    cudaGetSymbolAddress((void**)&wqkv,  g_wqkv);
    cudaGetSymbolAddress((void**)&wproj, g_wproj);
    cudaGetSymbolAddress((void**)&wfc1,  g_wfc1);
    cudaGetSymbolAddress((void**)&wfc2,  g_wfc2);

    cudaFuncSetAttribute(attn_tc_kernel, cudaFuncAttributeMaxDynamicSharedMemorySize,
                         ATTN_SMEM_BYTES);

    cvt_kernel<<<(3 * CDIM * CDIM + 255) / 256, 256>>>(qkv_w, wqkv, 3 * CDIM * CDIM);
    cvt_kernel<<<(CDIM * CDIM + 255) / 256, 256>>>(proj_w, wproj, CDIM * CDIM);
    cvt_kernel<<<(HID * CDIM + 255) / 256, 256>>>(fc1_w, wfc1, HID * CDIM);
    cvt_kernel<<<(CDIM * HID + 255) / 256, 256>>>(fc2_w, wfc2, CDIM * HID);

    bias_pre_kernel<<<(NN + 255) / 256, 256>>>(relidx, table, bias6);
    ln1_kernel<<<TOK, CDIM>>>(x, n1g, n1b, xwb);
    // QKV: (43904 x 576 x 192) -> bf16
    gemm_mma_kernel<3><<<dim3(576 / BN, TOK / BM), 256>>>(xwb, wqkv, qkv_b, nullptr, qkvb, CDIM, 3 * CDIM);
    // attention -> bf16
    attn_tc_kernel<<<dim3(TOTWIN * HEADS, NCH), 256, ATTN_SMEM_BYTES>>>(qkvb, bias6, mask, attnb);
    // proj: (43904 x 192 x 192) -> fp32
    gemm_mma_kernel<0><<<dim3(CDIM / BN, TOK / BM), 256>>>(attnb, wproj, proj_b, nullptr, proj, CDIM, CDIM);
    ln2res_kernel<<<TOK, CDIM>>>(x, proj, n2g, n2b, xres, ln2b);
    // FC1 + GELU: (43904 x 768 x 192) -> bf16
    gemm_mma_kernel<1><<<dim3(HID / BN, TOK / BM), 256>>>(ln2b, wfc1, fc1_b, nullptr, h1b, CDIM, HID);
    // FC2 + residual: (43904 x 192 x 768) -> fp32 out
    gemm_mma_kernel<2><<<dim3(CDIM / BN, TOK / BM), 256>>>(h1b, wfc2, fc2_b, xres, out, HID, CDIM);
}

// round 5
// speedup vs baseline: 7.0141x; 1.1345x over previous
#include <cuda_runtime.h>
#include <cuda_bf16.h>
#include <math.h>
#include <stdint.h>

// ---------------- problem constants ----------------
#define BATCH   2
#define DSZ     28
#define WS      7
#define SHIFT_  3
#define CDIM    192
#define HEADS   6
#define HD      32
#define NTOK    343
#define NWIN    64
#define TOTWIN  128
#define TOK     43904
#define HID     768
#define NN      117649
#define SCALE   0.17677669529663687f
#define TBLLEN  2197          // 13^3

// GEMM tiling
#define BM      128
#define BN      64
#define KB      64
#define GEMM_SMEM_BYTES 73728

// attention tiling
#define QT      64
#define NC      64
#define KPAD    384
#define NCH     6
#define QPITCH  80
#define KPITCH  80
#define VPITCH  784
#define PPITCH  144
// smem offsets (bytes)
#define AOFF_K   0
#define AOFF_V   30720
#define AOFF_Q   55808
#define AOFF_P   60928
#define AOFF_RS  70144
#define AOFF_TBL 70656
#define AOFF_KC  79444
#define ATTN_SMEM_BYTES 80992

// ---------------- scratch (device globals) ----------------
__device__ __nv_bfloat16 g_xwb [TOK * CDIM];
__device__ __nv_bfloat16 g_qkvb[TOK * 3 * CDIM];
__device__ __nv_bfloat16 g_attnb[TOK * CDIM];
__device__ float         g_proj[TOK * CDIM];
__device__ float         g_xres[TOK * CDIM];
__device__ __nv_bfloat16 g_ln2b[TOK * CDIM];
__device__ __nv_bfloat16 g_h1b [TOK * HID];
__device__ __nv_bfloat16 g_wqkv[3 * CDIM * CDIM];
__device__ __nv_bfloat16 g_wproj[CDIM * CDIM];
__device__ __nv_bfloat16 g_wfc1[HID * CDIM];
__device__ __nv_bfloat16 g_wfc2[CDIM * HID];

// ---------------- helpers ----------------
__device__ __forceinline__ uint32_t s2u(const void* p) {
    uint32_t r;
    asm("{ .reg .u64 t; cvta.to.shared.u64 t, %1; cvt.u32.u64 %0, t; }" : "=r"(r) : "l"(p));
    return r;
}
__device__ __forceinline__ float warpSum(float v) {
#pragma unroll
    for (int o = 16; o; o >>= 1) v += __shfl_xor_sync(0xffffffffu, v, o);
    return v;
}
__device__ __forceinline__ int token_to_winrow(int t) {
    int b   = t / (DSZ * DSZ * DSZ);
    int rem = t - b * (DSZ * DSZ * DSZ);
    int dd  = rem / (DSZ * DSZ);
    int hh  = (rem / DSZ) % DSZ;
    int ww  = rem % DSZ;
    int i = (dd + DSZ - SHIFT_) % DSZ;
    int j = (hh + DSZ - SHIFT_) % DSZ;
    int k = (ww + DSZ - SHIFT_) % DSZ;
    int win = (i / WS) * 16 + (j / WS) * 4 + (k / WS);
    int n   = (i % WS) * 49 + (j % WS) * 7 + (k % WS);
    return (b * NWIN + win) * NTOK + n;
}

#define CP_ASYNC16(dst_u32, src_ptr) \
    asm volatile("cp.async.cg.shared.global [%0], [%1], 16;" :: "r"(dst_u32), "l"(src_ptr))
#define CP_COMMIT() asm volatile("cp.async.commit_group;")
#define CP_WAIT(n)  asm volatile("cp.async.wait_group %0;" :: "n"(n))

#define LDMX4(r0, r1, r2, r3, addr) \
    asm volatile("ldmatrix.sync.aligned.m8n8.x4.shared.b16 {%0,%1,%2,%3}, [%4];" \
                 : "=r"(r0), "=r"(r1), "=r"(r2), "=r"(r3) : "r"(addr))

#define MMA16816(d, a0, a1, a2, a3, b0, b1) \
    asm volatile("mma.sync.aligned.m16n8k16.row.col.f32.bf16.bf16.f32 " \
                 "{%0,%1,%2,%3}, {%4,%5,%6,%7}, {%8,%9}, {%0,%1,%2,%3};" \
                 : "+f"((d)[0]), "+f"((d)[1]), "+f"((d)[2]), "+f"((d)[3]) \
                 : "r"(a0), "r"(a1), "r"(a2), "r"(a3), "r"(b0), "r"(b1))

// ---------------- merged weight conversion (4 segments) ----------------
__global__ void cvt4_kernel(const float* __restrict__ s0, __nv_bfloat16* __restrict__ d0, int n0,
                            const float* __restrict__ s1, __nv_bfloat16* __restrict__ d1, int n1,
                            const float* __restrict__ s2, __nv_bfloat16* __restrict__ d2, int n2,
                            const float* __restrict__ s3, __nv_bfloat16* __restrict__ d3, int n3) {
    int i = blockIdx.x * 256 + threadIdx.x;
    if (i < n0) { d0[i] = __float2bfloat16(s0[i]); return; }
    i -= n0;
    if (i < n1) { d1[i] = __float2bfloat16(s1[i]); return; }
    i -= n1;
    if (i < n2) { d2[i] = __float2bfloat16(s2[i]); return; }
    i -= n2;
    if (i < n3) { d3[i] = __float2bfloat16(s3[i]); }
}

// ---------------- LN1 + shift + window partition ----------------
__global__ __launch_bounds__(CDIM) void ln1_kernel(const float* __restrict__ x,
                                                   const float* __restrict__ g,
                                                   const float* __restrict__ b,
                                                   __nv_bfloat16* __restrict__ xw) {
    __shared__ float red[12];
    int t = blockIdx.x;
    int c = threadIdx.x;
    float v = x[(size_t)t * CDIM + c];
    float s  = warpSum(v);
    float s2 = warpSum(v * v);
    int w = c >> 5;
    if ((c & 31) == 0) { red[w] = s; red[6 + w] = s2; }
    __syncthreads();
    float ts = 0.f, ts2 = 0.f;
#pragma unroll
    for (int i = 0; i < 6; i++) { ts += red[i]; ts2 += red[6 + i]; }
    float mean = ts * (1.0f / CDIM);
    float var  = ts2 * (1.0f / CDIM) - mean * mean;
    float o = (v - mean) * rsqrtf(var + 1e-5f) * g[c] + b[c];
    int row = token_to_winrow(t);
    xw[(size_t)row * CDIM + c] = __float2bfloat16(o);
}

// ---------------- GEMM tile loader (cp.async, one K-chunk) ----------------
__device__ __forceinline__ void gemm_issue(const __nv_bfloat16* __restrict__ A,
                                           const __nv_bfloat16* __restrict__ Wt,
                                           int bm, int bn, int Ktot, int lr, int lc8,
                                           char* bA, char* bB, int k0) {
#pragma unroll
    for (int rr = 0; rr < 4; rr++) {
        int r = lr + rr * 32;
        uint32_t off = (uint32_t)(r * 128 + lc8 * 2);
        off ^= (off >> 3) & 0x70;
        CP_ASYNC16(s2u(bA + off), A + (size_t)(bm + r) * Ktot + k0 + lc8);
    }
#pragma unroll
    for (int rr = 0; rr < 2; rr++) {
        int br = lr + rr * 32;
        uint32_t off = (uint32_t)(br * 128 + lc8 * 2);
        off ^= (off >> 3) & 0x70;
        CP_ASYNC16(s2u(bB + off), Wt + (size_t)(bn + br) * Ktot + k0 + lc8);
    }
    CP_COMMIT();
}

// ---------------- HMMA bf16 GEMM, 3-stage cp.async pipeline ----------------
// EPI: 0 = bias -> fp32; 1 = bias+gelu -> bf16; 2 = bias+resid -> fp32; 3 = bias -> bf16
template <int EPI>
__global__ __launch_bounds__(256)
void gemm_mma_kernel(const __nv_bfloat16* __restrict__ A,
                     const __nv_bfloat16* __restrict__ Wt,
                     const float* __restrict__ bias,
                     const float* __restrict__ resid,
                     void* __restrict__ Cv, int Ktot, int Ntot)
{
    extern __shared__ __align__(1024) char dsm[];
    char* bufA[3] = {dsm, dsm + 16384, dsm + 32768};
    char* bufB[3] = {dsm + 49152, dsm + 57344, dsm + 65536};

    const int tid = threadIdx.x;
    const int lane = tid & 31;
    const int wid = tid >> 5;
    const int wm = (wid & 3) * 32;
    const int wn = (wid >> 2) * 32;
    const int bm = blockIdx.y * BM;
    const int bn = blockIdx.x * BN;

    float acc[2][4][4];
#pragma unroll
    for (int a = 0; a < 2; a++)
#pragma unroll
        for (int b = 0; b < 4; b++)
#pragma unroll
            for (int c = 0; c < 4; c++) acc[a][b][c] = 0.f;

    const int lr = tid >> 3;
    const int lc8 = (tid & 7) * 8;
    const int nch = Ktot / KB;

    gemm_issue(A, Wt, bm, bn, Ktot, lr, lc8, bufA[0], bufB[0], 0);
    if (nch > 1) gemm_issue(A, Wt, bm, bn, Ktot, lr, lc8, bufA[1], bufB[1], KB);

    for (int ch = 0; ch < nch; ch++) {
        if (ch + 2 < nch)
            gemm_issue(A, Wt, bm, bn, Ktot, lr, lc8,
                       bufA[(ch + 2) % 3], bufB[(ch + 2) % 3], (ch + 2) * KB);
        const int rem = nch - ch - 1;
        if (rem >= 2)      CP_WAIT(2);
        else if (rem == 1) CP_WAIT(1);
        else               CP_WAIT(0);
        __syncthreads();

        const uint32_t sA = s2u(bufA[ch % 3]);
        const uint32_t sB = s2u(bufB[ch % 3]);
#pragma unroll
        for (int ks = 0; ks < KB / 16; ks++) {
            uint32_t a0[2], a1[2], a2[2], a3[2];
#pragma unroll
            for (int mi = 0; mi < 2; mi++) {
                uint32_t off = (uint32_t)((wm + mi * 16 + (lane & 15)) * 128 + ks * 32 + (lane >> 4) * 16);
                off ^= (off >> 3) & 0x70;
                LDMX4(a0[mi], a1[mi], a2[mi], a3[mi], sA + off);
            }
#pragma unroll
            for (int nj = 0; nj < 2; nj++) {
                uint32_t off = (uint32_t)((wn + nj * 16 + (lane & 15)) * 128 + ks * 32 + (lane >> 4) * 16);
                off ^= (off >> 3) & 0x70;
                uint32_t r0, r1, r2, r3;
                LDMX4(r0, r1, r2, r3, sB + off);
#pragma unroll
                for (int mi = 0; mi < 2; mi++) {
                    MMA16816(acc[mi][2 * nj], a0[mi], a1[mi], a2[mi], a3[mi], r0, r2);
                    MMA16816(acc[mi][2 * nj + 1], a0[mi], a1[mi], a2[mi], a3[mi], r1, r3);
                }
            }
        }
        __syncthreads();
    }

    const int gq = lane >> 2;
    const int tg = lane & 3;
#pragma unroll
    for (int mi = 0; mi < 2; mi++) {
#pragma unroll
        for (int ni = 0; ni < 4; ni++) {
            int col = bn + wn + ni * 8 + tg * 2;
            float bia0 = bias[col], bia1 = bias[col + 1];
#pragma unroll
            for (int half = 0; half < 2; half++) {
                int row = bm + wm + mi * 16 + gq + half * 8;
                float v0 = acc[mi][ni][half * 2 + 0] + bia0;
                float v1 = acc[mi][ni][half * 2 + 1] + bia1;
                size_t oi = (size_t)row * Ntot + col;
                if (EPI == 1) {
                    v0 = 0.5f * v0 * (1.0f + erff(v0 * 0.7071067811865476f));
                    v1 = 0.5f * v1 * (1.0f + erff(v1 * 0.7071067811865476f));
                    __nv_bfloat162 p;
                    p.x = __float2bfloat16(v0); p.y = __float2bfloat16(v1);
                    *(__nv_bfloat162*)((__nv_bfloat16*)Cv + oi) = p;
                } else if (EPI == 2) {
                    float2 rv = *(const float2*)(resid + oi);
                    float2 o; o.x = v0 + rv.x; o.y = v1 + rv.y;
                    *(float2*)((float*)Cv + oi) = o;
                } else if (EPI == 3) {
                    __nv_bfloat162 p;
                    p.x = __float2bfloat16(v0); p.y = __float2bfloat16(v1);
                    *(__nv_bfloat162*)((__nv_bfloat16*)Cv + oi) = p;
                } else {
                    float2 o; o.x = v0; o.y = v1;
                    *(float2*)((float*)Cv + oi) = o;
                }
            }
        }
    }
}

// ---------------- tensor-core attention, bias/mask computed on the fly ----------------
// grid (TOTWIN*HEADS, 6); block 256.
__global__ __launch_bounds__(256) void attn_tc_kernel(
    const __nv_bfloat16* __restrict__ qkv, const float* __restrict__ table,
    __nv_bfloat16* __restrict__ out)
{
    extern __shared__ __align__(1024) char sm[];
    const uint32_t uK = s2u(sm + AOFF_K);
    const uint32_t uV = s2u(sm + AOFF_V);
    const uint32_t uQ = s2u(sm + AOFF_Q);
    const uint32_t uP = s2u(sm + AOFF_P);
    float* rs    = (float*)(sm + AOFF_RS);
    float* tbl_s = (float*)(sm + AOFF_TBL);
    int*   kc_s  = (int*)  (sm + AOFF_KC);

    const int bx = blockIdx.x;
    const int w  = bx / HEADS;
    const int h  = bx - w * HEADS;
    const int mw = w % NWIN;
    const int wd = mw >> 4, wh = (mw >> 2) & 3, ww = mw & 3;
    const int q0 = blockIdx.y * QT;
    const int tid = threadIdx.x;
    const int lane = tid & 31;
    const int wid = tid >> 5;

    const __nv_bfloat16* base = qkv + (size_t)w * NTOK * (3 * CDIM);

    // per-head bias table -> smem
    for (int r = tid; r < TBLLEN; r += 256)
        tbl_s[r] = table[r * HEADS + h];
    // packed coords + region id per token
    for (int n = tid; n < KPAD; n += 256) {
        int val = 0;
        if (n < NTOK) {
            int i = n / 49, rem = n - i * 49;
            int j = rem / 7, k = rem - j * 7;
            int dreg = (wd == 3) ? ((i < 4) ? 1 : 2) : 0;
            int hreg = (wh == 3) ? ((j < 4) ? 1 : 2) : 0;
            int wreg = (ww == 3) ? ((k < 4) ? 1 : 2) : 0;
            int rid = dreg * 9 + hreg * 3 + wreg;
            int pack = i * 169 + j * 13 + k;
            val = (pack << 8) | rid;
        }
        kc_s[n] = val;
    }
    // K tile (zero-padded)
    for (int idx = tid; idx < KPAD * 4; idx += 256) {
        int j = idx >> 2, s = idx & 3;
        uint4 v = make_uint4(0, 0, 0, 0);
        if (j < NTOK) v = *(const uint4*)(base + (size_t)j * (3 * CDIM) + CDIM + h * HD + s * 8);
        *(uint4*)(sm + AOFF_K + j * KPITCH + s * 16) = v;
    }
    // Q tile
    for (int idx = tid; idx < QT * 4; idx += 256) {
        int r = idx >> 2, s = idx & 3;
        int gq = q0 + r;
        uint4 v = make_uint4(0, 0, 0, 0);
        if (gq < NTOK) v = *(const uint4*)(base + (size_t)gq * (3 * CDIM) + h * HD + s * 8);
        *(uint4*)(sm + AOFF_Q + r * QPITCH + s * 16) = v;
    }
    // V transposed
    for (int j = tid; j < KPAD; j += 256) {
        __nv_bfloat16 tmp[32];
        if (j < NTOK) {
            const __nv_bfloat16* vp = base + (size_t)j * (3 * CDIM) + 2 * CDIM + h * HD;
#pragma unroll
            for (int s = 0; s < 4; s++) *(uint4*)(tmp + s * 8) = *(const uint4*)(vp + s * 8);
        } else {
#pragma unroll
            for (int d = 0; d < 32; d++) tmp[d] = __float2bfloat16(0.f);
        }
#pragma unroll
        for (int d = 0; d < 32; d++)
            *(__nv_bfloat16*)(sm + AOFF_V + d * VPITCH + j * 2) = tmp[d];
    }
    __syncthreads();

    const int wm = wid & 3, wn = wid >> 2;       // S layout
    const int vm = wid & 1, vn = wid >> 1;       // PV layout
    const int gq_ = lane >> 2, tg = lane & 3;

    float acc_o[2][4];
#pragma unroll
    for (int t = 0; t < 2; t++)
#pragma unroll
        for (int c = 0; c < 4; c++) acc_o[t][c] = 0.f;
    float rs0 = 0.f, rs1 = 0.f;

    const int r0g = q0 + wm * 16 + gq_;
    const int r1g = r0g + 8;
    const bool v0 = (r0g < NTOK);
    const bool v1 = (r1g < NTOK);
    const int qv0 = v0 ? kc_s[r0g] : 0;
    const int qv1 = v1 ? kc_s[r1g] : 0;
    const int qbase0 = (qv0 >> 8) + 1098, qrid0 = qv0 & 255;
    const int qbase1 = (qv1 >> 8) + 1098, qrid1 = qv1 & 255;

    for (int ch = 0; ch < NCH; ch++) {
        const int j0 = ch * NC;
        float acc[4][4];
#pragma unroll
        for (int t = 0; t < 4; t++)
#pragma unroll
            for (int c = 0; c < 4; c++) acc[t][c] = 0.f;

        // S = Q @ K^T
#pragma unroll
        for (int ks = 0; ks < 2; ks++) {
            uint32_t a0, a1, a2, a3;
            LDMX4(a0, a1, a2, a3,
                  uQ + (uint32_t)((wm * 16 + (lane & 15)) * QPITCH + ks * 32 + (lane >> 4) * 16));
#pragma unroll
            for (int nj = 0; nj < 2; nj++) {
                uint32_t r0, r1, r2, r3;
                LDMX4(r0, r1, r2, r3,
                      uK + (uint32_t)((j0 + wn * 32 + nj * 16 + (lane & 15)) * KPITCH + ks * 32 + (lane >> 4) * 16));
                MMA16816(acc[2 * nj], a0, a1, a2, a3, r0, r2);
                MMA16816(acc[2 * nj + 1], a0, a1, a2, a3, r1, r3);
            }
        }

        // epilogue: exp(scale*s + bias + mask) -> P, rowsums
#pragma unroll
        for (int ti = 0; ti < 4; ti++) {
            int jl = wn * 32 + (ti >> 1) * 16 + (ti & 1) * 8 + tg * 2;
            int ja = j0 + jl, jb = ja + 1;
            float e00 = 0.f, e01 = 0.f, e10 = 0.f, e11 = 0.f;
            if (ja < NTOK) {
                int kv = kc_s[ja];
                int kp = kv >> 8, kr = kv & 255;
                if (v0) {
                    float add = tbl_s[qbase0 - kp] + ((qrid0 == kr) ? 0.f : -100.f);
                    e00 = __expf(fmaf(acc[ti][0], SCALE, add));
                }
                if (v1) {
                    float add = tbl_s[qbase1 - kp] + ((qrid1 == kr) ? 0.f : -100.f);
                    e10 = __expf(fmaf(acc[ti][2], SCALE, add));
                }
            }
            if (jb < NTOK) {
                int kv = kc_s[jb];
                int kp = kv >> 8, kr = kv & 255;
                if (v0) {
                    float add = tbl_s[qbase0 - kp] + ((qrid0 == kr) ? 0.f : -100.f);
                    e01 = __expf(fmaf(acc[ti][1], SCALE, add));
                }
                if (v1) {
                    float add = tbl_s[qbase1 - kp] + ((qrid1 == kr) ? 0.f : -100.f);
                    e11 = __expf(fmaf(acc[ti][3], SCALE, add));
                }
            }
            rs0 += e00 + e01;
            rs1 += e10 + e11;
            __nv_bfloat162 p0, p1;
            p0.x = __float2bfloat16(e00); p0.y = __float2bfloat16(e01);
            p1.x = __float2bfloat16(e10); p1.y = __float2bfloat16(e11);
            int rloc0 = wm * 16 + gq_;
            *(__nv_bfloat162*)(sm + AOFF_P + rloc0 * PPITCH + jl * 2) = p0;
            *(__nv_bfloat162*)(sm + AOFF_P + (rloc0 + 8) * PPITCH + jl * 2) = p1;
        }
        __syncthreads();

        // O^T += V^T @ P^T
#pragma unroll
        for (int kk = 0; kk < 4; kk++) {
            uint32_t a0, a1, a2, a3;
            LDMX4(a0, a1, a2, a3,
                  uV + (uint32_t)((vm * 16 + (lane & 15)) * VPITCH + j0 * 2 + kk * 32 + (lane >> 4) * 16));
            uint32_t r0, r1, r2, r3;
            LDMX4(r0, r1, r2, r3,
                  uP + (uint32_t)((vn * 16 + (lane & 15)) * PPITCH + kk * 32 + (lane >> 4) * 16));
            MMA16816(acc_o[0], a0, a1, a2, a3, r0, r2);
            MMA16816(acc_o[1], a0, a1, a2, a3, r1, r3);
        }
        __syncthreads();
    }

    // rowsums
    rs0 += __shfl_xor_sync(0xffffffffu, rs0, 1);
    rs0 += __shfl_xor_sync(0xffffffffu, rs0, 2);
    rs1 += __shfl_xor_sync(0xffffffffu, rs1, 1);
    rs1 += __shfl_xor_sync(0xffffffffu, rs1, 2);
    if (tg == 0) {
        rs[(wm * 16 + gq_) * 2 + wn] = rs0;
        rs[(wm * 16 + gq_ + 8) * 2 + wn] = rs1;
    }

    // stage O^T (reuse P region)
    float* Ost = (float*)(sm + AOFF_P);
#pragma unroll
    for (int t = 0; t < 2; t++) {
        int qc = vn * 16 + t * 8 + tg * 2;
        int d0 = vm * 16 + gq_;
        Ost[d0 * 65 + qc]     = acc_o[t][0];
        Ost[d0 * 65 + qc + 1] = acc_o[t][1];
        Ost[(d0 + 8) * 65 + qc]     = acc_o[t][2];
        Ost[(d0 + 8) * 65 + qc + 1] = acc_o[t][3];
    }
    __syncthreads();

    {
        int q = tid >> 2, ds = (tid & 3) * 8;
        int gq = q0 + q;
        if (gq < NTOK) {
            float inv = __frcp_rn(rs[q * 2] + rs[q * 2 + 1]);
            __nv_bfloat16 o[8];
#pragma unroll
            for (int u = 0; u < 8; u++)
                o[u] = __float2bfloat16(Ost[(ds + u) * 65 + q] * inv);
            *(uint4*)(out + (size_t)(w * NTOK + gq) * CDIM + h * HD + ds) = *(uint4*)o;
        }
    }
}

// ---------------- reverse + residual + LN2 ----------------
__global__ __launch_bounds__(CDIM) void ln2res_kernel(const float* __restrict__ x,
                                                      const float* __restrict__ proj,
                                                      const float* __restrict__ g,
                                                      const float* __restrict__ b,
                                                      float* __restrict__ xres,
                                                      __nv_bfloat16* __restrict__ ln2o) {
    __shared__ float red[12];
    int t = blockIdx.x;
    int c = threadIdx.x;
    int row = token_to_winrow(t);
    float v = x[(size_t)t * CDIM + c] + proj[(size_t)row * CDIM + c];
    xres[(size_t)t * CDIM + c] = v;

    float s  = warpSum(v);
    float s2 = warpSum(v * v);
    int w = c >> 5;
    if ((c & 31) == 0) { red[w] = s; red[6 + w] = s2; }
    __syncthreads();
    float ts = 0.f, ts2 = 0.f;
#pragma unroll
    for (int i = 0; i < 6; i++) { ts += red[i]; ts2 += red[6 + i]; }
    float mean = ts * (1.0f / CDIM);
    float var  = ts2 * (1.0f / CDIM) - mean * mean;
    ln2o[(size_t)t * CDIM + c] = __float2bfloat16((v - mean) * rsqrtf(var + 1e-5f) * g[c] + b[c]);
}

// ---------------- launch ----------------
extern "C" void kernel_launch(void* const* d_in, const int* in_sizes, int n_in,
                              void* d_out, int out_size) {
    (void)in_sizes; (void)n_in; (void)out_size;
    const float* x       = (const float*)d_in[0];
    const float* table   = (const float*)d_in[3];
    const float* n1g     = (const float*)d_in[4];
    const float* n1b     = (const float*)d_in[5];
    const float* qkv_w   = (const float*)d_in[6];
    const float* qkv_b   = (const float*)d_in[7];
    const float* proj_w  = (const float*)d_in[8];
    const float* proj_b  = (const float*)d_in[9];
    const float* n2g     = (const float*)d_in[10];
    const float* n2b     = (const float*)d_in[11];
    const float* fc1_w   = (const float*)d_in[12];
    const float* fc1_b   = (const float*)d_in[13];
    const float* fc2_w   = (const float*)d_in[14];
    const float* fc2_b   = (const float*)d_in[15];
    float* out = (float*)d_out;

    __nv_bfloat16 *xwb, *qkvb, *attnb, *ln2b, *h1b, *wqkv, *wproj, *wfc1, *wfc2;
    float *proj, *xres;
    cudaGetSymbolAddress((void**)&xwb,   g_xwb);
    cudaGetSymbolAddress((void**)&qkvb,  g_qkvb);
    cudaGetSymbolAddress((void**)&attnb, g_attnb);
    cudaGetSymbolAddress((void**)&proj,  g_proj);
    cudaGetSymbolAddress((void**)&xres,  g_xres);
    cudaGetSymbolAddress((void**)&ln2b,  g_ln2b);
    cudaGetSymbolAddress((void**)&h1b,   g_h1b);
    cudaGetSymbolAddress((void**)&wqkv,  g_wqkv);
    cudaGetSymbolAddress((void**)&wproj, g_wproj);
    cudaGetSymbolAddress((void**)&wfc1,  g_wfc1);
    cudaGetSymbolAddress((void**)&wfc2,  g_wfc2);

    cudaFuncSetAttribute(attn_tc_kernel, cudaFuncAttributeMaxDynamicSharedMemorySize,
                         ATTN_SMEM_BYTES);
    cudaFuncSetAttribute(gemm_mma_kernel<0>, cudaFuncAttributeMaxDynamicSharedMemorySize, GEMM_SMEM_BYTES);
    cudaFuncSetAttribute(gemm_mma_kernel<1>, cudaFuncAttributeMaxDynamicSharedMemorySize, GEMM_SMEM_BYTES);
    cudaFuncSetAttribute(gemm_mma_kernel<2>, cudaFuncAttributeMaxDynamicSharedMemorySize, GEMM_SMEM_BYTES);
    cudaFuncSetAttribute(gemm_mma_kernel<3>, cudaFuncAttributeMaxDynamicSharedMemorySize, GEMM_SMEM_BYTES);

    const int n0 = 3 * CDIM * CDIM, n1 = CDIM * CDIM, n2 = HID * CDIM, n3 = CDIM * HID;
    cvt4_kernel<<<(n0 + n1 + n2 + n3 + 255) / 256, 256>>>(
        qkv_w, wqkv, n0, proj_w, wproj, n1, fc1_w, wfc1, n2, fc2_w, wfc2, n3);

    ln1_kernel<<<TOK, CDIM>>>(x, n1g, n1b, xwb);
    // QKV: (43904 x 576 x 192) -> bf16
    gemm_mma_kernel<3><<<dim3(576 / BN, TOK / BM), 256, GEMM_SMEM_BYTES>>>(
        xwb, wqkv, qkv_b, nullptr, qkvb, CDIM, 3 * CDIM);
    // attention -> bf16
    attn_tc_kernel<<<dim3(TOTWIN * HEADS, NCH), 256, ATTN_SMEM_BYTES>>>(qkvb, table, attnb);
    // proj: (43904 x 192 x 192) -> fp32
    gemm_mma_kernel<0><<<dim3(CDIM / BN, TOK / BM), 256, GEMM_SMEM_BYTES>>>(
        attnb, wproj, proj_b, nullptr, proj, CDIM, CDIM);
    ln2res_kernel<<<TOK, CDIM>>>(x, proj, n2g, n2b, xres, ln2b);
    // FC1 + GELU: (43904 x 768 x 192) -> bf16
    gemm_mma_kernel<1><<<dim3(HID / BN, TOK / BM), 256, GEMM_SMEM_BYTES>>>(
        ln2b, wfc1, fc1_b, nullptr, h1b, CDIM, HID);
    // FC2 + residual: (43904 x 192 x 768) -> fp32 out
    gemm_mma_kernel<2><<<dim3(CDIM / BN, TOK / BM), 256, GEMM_SMEM_BYTES>>>(
        h1b, wfc2, fc2_b, xres, out, HID, CDIM);
}

// round 6
// speedup vs baseline: 7.5440x; 1.0755x over previous
#include <cuda_runtime.h>
#include <cuda_bf16.h>
#include <math.h>
#include <stdint.h>

// ---------------- problem constants ----------------
#define BATCH   2
#define DSZ     28
#define WS      7
#define SHIFT_  3
#define CDIM    192
#define HEADS   6
#define HD      32
#define NTOK    343
#define NWIN    64
#define TOTWIN  128
#define TOK     43904
#define HID     768
#define SCALE   0.17677669529663687f

// GEMM tiling
#define BM      128
#define BN      64
#define KB      64
#define GEMM_SMEM_BYTES 73728

// attention tiling
#define QT      64
#define NC      64
#define KPAD    384
#define NCH     6
#define QPITCH  80
#define KPITCH  80
#define VPITCH  784
#define PPITCH  144
#define CPITCH  344
// smem offsets (bytes)
#define AOFF_K   0
#define AOFF_V   30720
#define AOFF_Q   55808
#define AOFF_P   60928
#define AOFF_RS  70144
#define ATTN_SMEM_BYTES 70656

#define COMB_ELEMS (48 * NTOK * CPITCH)

// ---------------- scratch (device globals) ----------------
__device__ __nv_bfloat16 g_xwb [TOK * CDIM];
__device__ __nv_bfloat16 g_qkvb[TOK * 3 * CDIM];
__device__ __nv_bfloat16 g_attnb[TOK * CDIM];
__device__ float         g_proj[TOK * CDIM];
__device__ float         g_xres[TOK * CDIM];
__device__ __nv_bfloat16 g_ln2b[TOK * CDIM];
__device__ __nv_bfloat16 g_h1b [TOK * HID];
__device__ __nv_bfloat16 g_wqkv[3 * CDIM * CDIM];
__device__ __nv_bfloat16 g_wproj[CDIM * CDIM];
__device__ __nv_bfloat16 g_wfc1[HID * CDIM];
__device__ __nv_bfloat16 g_wfc2[CDIM * HID];
__device__ __nv_bfloat16 g_comb[COMB_ELEMS];   // [head][maskclass][row][colpad]

// ---------------- helpers ----------------
__device__ __forceinline__ uint32_t s2u(const void* p) {
    uint32_t r;
    asm("{ .reg .u64 t; cvta.to.shared.u64 t, %1; cvt.u32.u64 %0, t; }" : "=r"(r) : "l"(p));
    return r;
}
__device__ __forceinline__ float warpSum(float v) {
#pragma unroll
    for (int o = 16; o; o >>= 1) v += __shfl_xor_sync(0xffffffffu, v, o);
    return v;
}
__device__ __forceinline__ int token_to_winrow(int t) {
    int b   = t / (DSZ * DSZ * DSZ);
    int rem = t - b * (DSZ * DSZ * DSZ);
    int dd  = rem / (DSZ * DSZ);
    int hh  = (rem / DSZ) % DSZ;
    int ww  = rem % DSZ;
    int i = (dd + DSZ - SHIFT_) % DSZ;
    int j = (hh + DSZ - SHIFT_) % DSZ;
    int k = (ww + DSZ - SHIFT_) % DSZ;
    int win = (i / WS) * 16 + (j / WS) * 4 + (k / WS);
    int n   = (i % WS) * 49 + (j % WS) * 7 + (k % WS);
    return (b * NWIN + win) * NTOK + n;
}

#define CP_ASYNC16(dst_u32, src_ptr) \
    asm volatile("cp.async.cg.shared.global [%0], [%1], 16;" :: "r"(dst_u32), "l"(src_ptr))
#define CP_COMMIT() asm volatile("cp.async.commit_group;")
#define CP_WAIT(n)  asm volatile("cp.async.wait_group %0;" :: "n"(n))

#define LDMX4(r0, r1, r2, r3, addr) \
    asm volatile("ldmatrix.sync.aligned.m8n8.x4.shared.b16 {%0,%1,%2,%3}, [%4];" \
                 : "=r"(r0), "=r"(r1), "=r"(r2), "=r"(r3) : "r"(addr))

#define MMA16816(d, a0, a1, a2, a3, b0, b1) \
    asm volatile("mma.sync.aligned.m16n8k16.row.col.f32.bf16.bf16.f32 " \
                 "{%0,%1,%2,%3}, {%4,%5,%6,%7}, {%8,%9}, {%0,%1,%2,%3};" \
                 : "+f"((d)[0]), "+f"((d)[1]), "+f"((d)[2]), "+f"((d)[3]) \
                 : "r"(a0), "r"(a1), "r"(a2), "r"(a3), "r"(b0), "r"(b1))

// ---------------- merged weight conversion ----------------
__global__ void cvt4_kernel(const float* __restrict__ s0, __nv_bfloat16* __restrict__ d0, int n0,
                            const float* __restrict__ s1, __nv_bfloat16* __restrict__ d1, int n1,
                            const float* __restrict__ s2, __nv_bfloat16* __restrict__ d2, int n2,
                            const float* __restrict__ s3, __nv_bfloat16* __restrict__ d3, int n3) {
    int i = blockIdx.x * 256 + threadIdx.x;
    if (i < n0) { d0[i] = __float2bfloat16(s0[i]); return; }
    i -= n0;
    if (i < n1) { d1[i] = __float2bfloat16(s1[i]); return; }
    i -= n1;
    if (i < n2) { d2[i] = __float2bfloat16(s2[i]); return; }
    i -= n2;
    if (i < n3) { d3[i] = __float2bfloat16(s3[i]); }
}

// ---------------- combined bias+mask precompute ----------------
// comb[h][cls][row][colpad] bf16; cls bit2=d-axis boundary, bit1=h, bit0=w
__global__ void comb_pre_kernel(const float* __restrict__ table,
                                __nv_bfloat16* __restrict__ comb) {
    int idx = blockIdx.x * 256 + threadIdx.x;
    if (idx >= COMB_ELEMS) return;
    int col  = idx % CPITCH;
    int rest = idx / CPITCH;
    int row  = rest % NTOK;
    int hc   = rest / NTOK;
    int h = hc >> 3, cls = hc & 7;
    float val = -100.f;
    if (col < NTOK) {
        int i3 = row / 49, j3 = (row / 7) % 7, k3 = row % 7;
        int ci = col / 49, cj = (col / 7) % 7, ck = col % 7;
        int rel = (i3 - ci + 6) * 169 + (j3 - cj + 6) * 13 + (k3 - ck + 6);
        val = table[rel * HEADS + h];
        bool diff = ((cls & 4) && ((i3 < 4) != (ci < 4))) ||
                    ((cls & 2) && ((j3 < 4) != (cj < 4))) ||
                    ((cls & 1) && ((k3 < 4) != (ck < 4)));
        if (diff) val -= 100.f;
    }
    comb[idx] = __float2bfloat16(val);
}

// ---------------- LN1 + shift + window partition ----------------
__global__ __launch_bounds__(CDIM) void ln1_kernel(const float* __restrict__ x,
                                                   const float* __restrict__ g,
                                                   const float* __restrict__ b,
                                                   __nv_bfloat16* __restrict__ xw) {
    __shared__ float red[12];
    int t = blockIdx.x;
    int c = threadIdx.x;
    float v = x[(size_t)t * CDIM + c];
    float s  = warpSum(v);
    float s2 = warpSum(v * v);
    int w = c >> 5;
    if ((c & 31) == 0) { red[w] = s; red[6 + w] = s2; }
    __syncthreads();
    float ts = 0.f, ts2 = 0.f;
#pragma unroll
    for (int i = 0; i < 6; i++) { ts += red[i]; ts2 += red[6 + i]; }
    float mean = ts * (1.0f / CDIM);
    float var  = ts2 * (1.0f / CDIM) - mean * mean;
    float o = (v - mean) * rsqrtf(var + 1e-5f) * g[c] + b[c];
    int row = token_to_winrow(t);
    xw[(size_t)row * CDIM + c] = __float2bfloat16(o);
}

// ---------------- GEMM tile loader ----------------
__device__ __forceinline__ void gemm_issue(const __nv_bfloat16* __restrict__ A,
                                           const __nv_bfloat16* __restrict__ Wt,
                                           int bm, int bn, int Ktot, int lr, int lc8,
                                           char* bA, char* bB, int k0) {
#pragma unroll
    for (int rr = 0; rr < 4; rr++) {
        int r = lr + rr * 32;
        uint32_t off = (uint32_t)(r * 128 + lc8 * 2);
        off ^= (off >> 3) & 0x70;
        CP_ASYNC16(s2u(bA + off), A + (size_t)(bm + r) * Ktot + k0 + lc8);
    }
#pragma unroll
    for (int rr = 0; rr < 2; rr++) {
        int br = lr + rr * 32;
        uint32_t off = (uint32_t)(br * 128 + lc8 * 2);
        off ^= (off >> 3) & 0x70;
        CP_ASYNC16(s2u(bB + off), Wt + (size_t)(bn + br) * Ktot + k0 + lc8);
    }
    CP_COMMIT();
}

// ---------------- HMMA bf16 GEMM, 3-stage cp.async pipeline ----------------
template <int EPI>
__global__ __launch_bounds__(256)
void gemm_mma_kernel(const __nv_bfloat16* __restrict__ A,
                     const __nv_bfloat16* __restrict__ Wt,
                     const float* __restrict__ bias,
                     const float* __restrict__ resid,
                     void* __restrict__ Cv, int Ktot, int Ntot)
{
    extern __shared__ __align__(1024) char dsm[];
    char* bufA[3] = {dsm, dsm + 16384, dsm + 32768};
    char* bufB[3] = {dsm + 49152, dsm + 57344, dsm + 65536};

    const int tid = threadIdx.x;
    const int lane = tid & 31;
    const int wid = tid >> 5;
    const int wm = (wid & 3) * 32;
    const int wn = (wid >> 2) * 32;
    const int bm = blockIdx.y * BM;
    const int bn = blockIdx.x * BN;

    float acc[2][4][4];
#pragma unroll
    for (int a = 0; a < 2; a++)
#pragma unroll
        for (int b = 0; b < 4; b++)
#pragma unroll
            for (int c = 0; c < 4; c++) acc[a][b][c] = 0.f;

    const int lr = tid >> 3;
    const int lc8 = (tid & 7) * 8;
    const int nch = Ktot / KB;

    gemm_issue(A, Wt, bm, bn, Ktot, lr, lc8, bufA[0], bufB[0], 0);
    if (nch > 1) gemm_issue(A, Wt, bm, bn, Ktot, lr, lc8, bufA[1], bufB[1], KB);

    for (int ch = 0; ch < nch; ch++) {
        if (ch + 2 < nch)
            gemm_issue(A, Wt, bm, bn, Ktot, lr, lc8,
                       bufA[(ch + 2) % 3], bufB[(ch + 2) % 3], (ch + 2) * KB);
        const int rem = nch - ch - 1;
        if (rem >= 2)      CP_WAIT(2);
        else if (rem == 1) CP_WAIT(1);
        else               CP_WAIT(0);
        __syncthreads();

        const uint32_t sA = s2u(bufA[ch % 3]);
        const uint32_t sB = s2u(bufB[ch % 3]);
#pragma unroll
        for (int ks = 0; ks < KB / 16; ks++) {
            uint32_t a0[2], a1[2], a2[2], a3[2];
#pragma unroll
            for (int mi = 0; mi < 2; mi++) {
                uint32_t off = (uint32_t)((wm + mi * 16 + (lane & 15)) * 128 + ks * 32 + (lane >> 4) * 16);
                off ^= (off >> 3) & 0x70;
                LDMX4(a0[mi], a1[mi], a2[mi], a3[mi], sA + off);
            }
#pragma unroll
            for (int nj = 0; nj < 2; nj++) {
                uint32_t off = (uint32_t)((wn + nj * 16 + (lane & 15)) * 128 + ks * 32 + (lane >> 4) * 16);
                off ^= (off >> 3) & 0x70;
                uint32_t r0, r1, r2, r3;
                LDMX4(r0, r1, r2, r3, sB + off);
#pragma unroll
                for (int mi = 0; mi < 2; mi++) {
                    MMA16816(acc[mi][2 * nj], a0[mi], a1[mi], a2[mi], a3[mi], r0, r2);
                    MMA16816(acc[mi][2 * nj + 1], a0[mi], a1[mi], a2[mi], a3[mi], r1, r3);
                }
            }
        }
        __syncthreads();
    }

    const int gq = lane >> 2;
    const int tg = lane & 3;
#pragma unroll
    for (int mi = 0; mi < 2; mi++) {
#pragma unroll
        for (int ni = 0; ni < 4; ni++) {
            int col = bn + wn + ni * 8 + tg * 2;
            float bia0 = bias[col], bia1 = bias[col + 1];
#pragma unroll
            for (int half = 0; half < 2; half++) {
                int row = bm + wm + mi * 16 + gq + half * 8;
                float v0 = acc[mi][ni][half * 2 + 0] + bia0;
                float v1 = acc[mi][ni][half * 2 + 1] + bia1;
                size_t oi = (size_t)row * Ntot + col;
                if (EPI == 1) {
                    v0 = 0.5f * v0 * (1.0f + erff(v0 * 0.7071067811865476f));
                    v1 = 0.5f * v1 * (1.0f + erff(v1 * 0.7071067811865476f));
                    __nv_bfloat162 p;
                    p.x = __float2bfloat16(v0); p.y = __float2bfloat16(v1);
                    *(__nv_bfloat162*)((__nv_bfloat16*)Cv + oi) = p;
                } else if (EPI == 2) {
                    float2 rv = *(const float2*)(resid + oi);
                    float2 o; o.x = v0 + rv.x; o.y = v1 + rv.y;
                    *(float2*)((float*)Cv + oi) = o;
                } else if (EPI == 3) {
                    __nv_bfloat162 p;
                    p.x = __float2bfloat16(v0); p.y = __float2bfloat16(v1);
                    *(__nv_bfloat162*)((__nv_bfloat16*)Cv + oi) = p;
                } else {
                    float2 o; o.x = v0; o.y = v1;
                    *(float2*)((float*)Cv + oi) = o;
                }
            }
        }
    }
}

// ---------------- tensor-core attention ----------------
// grid (TOTWIN*HEADS, 6); block 256, 3 CTAs/SM.
__global__ __launch_bounds__(256, 3) void attn_tc_kernel(
    const __nv_bfloat16* __restrict__ qkv, const __nv_bfloat16* __restrict__ comb,
    __nv_bfloat16* __restrict__ out)
{
    extern __shared__ __align__(1024) char sm[];
    const uint32_t uK = s2u(sm + AOFF_K);
    const uint32_t uV = s2u(sm + AOFF_V);
    const uint32_t uQ = s2u(sm + AOFF_Q);
    const uint32_t uP = s2u(sm + AOFF_P);
    float* rs = (float*)(sm + AOFF_RS);

    const int bx = blockIdx.x;
    const int w  = bx / HEADS;
    const int h  = bx - w * HEADS;
    const int mw = w % NWIN;
    const int wd = mw >> 4, wh = (mw >> 2) & 3, ww = mw & 3;
    const int cls = ((wd == 3) << 2) | ((wh == 3) << 1) | (ww == 3);
    const int q0 = blockIdx.y * QT;
    const int tid = threadIdx.x;
    const int lane = tid & 31;
    const int wid = tid >> 5;

    const __nv_bfloat16* base = qkv + (size_t)w * NTOK * (3 * CDIM);

    // K tile (zero-padded)
    for (int idx = tid; idx < KPAD * 4; idx += 256) {
        int j = idx >> 2, s = idx & 3;
        uint4 v = make_uint4(0, 0, 0, 0);
        if (j < NTOK) v = *(const uint4*)(base + (size_t)j * (3 * CDIM) + CDIM + h * HD + s * 8);
        *(uint4*)(sm + AOFF_K + j * KPITCH + s * 16) = v;
    }
    // Q tile
    for (int idx = tid; idx < QT * 4; idx += 256) {
        int r = idx >> 2, s = idx & 3;
        int gq = q0 + r;
        uint4 v = make_uint4(0, 0, 0, 0);
        if (gq < NTOK) v = *(const uint4*)(base + (size_t)gq * (3 * CDIM) + h * HD + s * 8);
        *(uint4*)(sm + AOFF_Q + r * QPITCH + s * 16) = v;
    }
    // V transposed, packed pair stores (4B, conflict-free)
    for (int jp = tid; jp < KPAD / 2; jp += 256) {
        int j0 = jp * 2;
        __nv_bfloat16 ta[32], tb[32];
        if (j0 < NTOK) {
            const __nv_bfloat16* vp = base + (size_t)j0 * (3 * CDIM) + 2 * CDIM + h * HD;
#pragma unroll
            for (int s = 0; s < 4; s++) *(uint4*)(ta + s * 8) = *(const uint4*)(vp + s * 8);
        } else {
#pragma unroll
            for (int d = 0; d < 32; d++) ta[d] = __float2bfloat16(0.f);
        }
        if (j0 + 1 < NTOK) {
            const __nv_bfloat16* vp = base + (size_t)(j0 + 1) * (3 * CDIM) + 2 * CDIM + h * HD;
#pragma unroll
            for (int s = 0; s < 4; s++) *(uint4*)(tb + s * 8) = *(const uint4*)(vp + s * 8);
        } else {
#pragma unroll
            for (int d = 0; d < 32; d++) tb[d] = __float2bfloat16(0.f);
        }
#pragma unroll
        for (int d = 0; d < 32; d++) {
            __nv_bfloat162 p; p.x = ta[d]; p.y = tb[d];
            *(__nv_bfloat162*)(sm + AOFF_V + d * VPITCH + j0 * 2) = p;
        }
    }
    __syncthreads();

    const int wm = wid & 3, wn = wid >> 2;       // S layout
    const int vm = wid & 1, vn = wid >> 1;       // PV layout
    const int gq_ = lane >> 2, tg = lane & 3;

    float acc_o[2][4];
#pragma unroll
    for (int t = 0; t < 2; t++)
#pragma unroll
        for (int c = 0; c < 4; c++) acc_o[t][c] = 0.f;
    float rs0 = 0.f, rs1 = 0.f;

    const int r0g = q0 + wm * 16 + gq_;
    const int r1g = r0g + 8;
    const bool v0 = (r0g < NTOK);
    const bool v1 = (r1g < NTOK);
    const __nv_bfloat16* cb = comb + (size_t)(h * 8 + cls) * NTOK * CPITCH;
    const __nv_bfloat16* c0p = cb + (size_t)r0g * CPITCH;
    const __nv_bfloat16* c1p = cb + (size_t)r1g * CPITCH;

    for (int ch = 0; ch < NCH; ch++) {
        const int j0 = ch * NC;
        float acc[4][4];
#pragma unroll
        for (int t = 0; t < 4; t++)
#pragma unroll
            for (int c = 0; c < 4; c++) acc[t][c] = 0.f;

        // S = Q @ K^T
#pragma unroll
        for (int ks = 0; ks < 2; ks++) {
            uint32_t a0, a1, a2, a3;
            LDMX4(a0, a1, a2, a3,
                  uQ + (uint32_t)((wm * 16 + (lane & 15)) * QPITCH + ks * 32 + (lane >> 4) * 16));
#pragma unroll
            for (int nj = 0; nj < 2; nj++) {
                uint32_t r0, r1, r2, r3;
                LDMX4(r0, r1, r2, r3,
                      uK + (uint32_t)((j0 + wn * 32 + nj * 16 + (lane & 15)) * KPITCH + ks * 32 + (lane >> 4) * 16));
                MMA16816(acc[2 * nj], a0, a1, a2, a3, r0, r2);
                MMA16816(acc[2 * nj + 1], a0, a1, a2, a3, r1, r3);
            }
        }

        // epilogue: exp(scale*s + comb) -> P, rowsums
#pragma unroll
        for (int ti = 0; ti < 4; ti++) {
            int jl = wn * 32 + (ti >> 1) * 16 + (ti & 1) * 8 + tg * 2;
            int ja = j0 + jl;
            float e00 = 0.f, e01 = 0.f, e10 = 0.f, e11 = 0.f;
            if (ja < NTOK) {
                if (v0) {
                    __nv_bfloat162 bp = *(const __nv_bfloat162*)(c0p + ja);
                    e00 = __expf(fmaf(acc[ti][0], SCALE, __bfloat162float(bp.x)));
                    e01 = __expf(fmaf(acc[ti][1], SCALE, __bfloat162float(bp.y)));
                }
                if (v1) {
                    __nv_bfloat162 bp = *(const __nv_bfloat162*)(c1p + ja);
                    e10 = __expf(fmaf(acc[ti][2], SCALE, __bfloat162float(bp.x)));
                    e11 = __expf(fmaf(acc[ti][3], SCALE, __bfloat162float(bp.y)));
                }
            }
            rs0 += e00 + e01;
            rs1 += e10 + e11;
            __nv_bfloat162 p0, p1;
            p0.x = __float2bfloat16(e00); p0.y = __float2bfloat16(e01);
            p1.x = __float2bfloat16(e10); p1.y = __float2bfloat16(e11);
            int rloc0 = wm * 16 + gq_;
            *(__nv_bfloat162*)(sm + AOFF_P + rloc0 * PPITCH + jl * 2) = p0;
            *(__nv_bfloat162*)(sm + AOFF_P + (rloc0 + 8) * PPITCH + jl * 2) = p1;
        }
        __syncthreads();

        // O^T += V^T @ P^T
#pragma unroll
        for (int kk = 0; kk < 4; kk++) {
            uint32_t a0, a1, a2, a3;
            LDMX4(a0, a1, a2, a3,
                  uV + (uint32_t)((vm * 16 + (lane & 15)) * VPITCH + j0 * 2 + kk * 32 + (lane >> 4) * 16));
            uint32_t r0, r1, r2, r3;
            LDMX4(r0, r1, r2, r3,
                  uP + (uint32_t)((vn * 16 + (lane & 15)) * PPITCH + kk * 32 + (lane >> 4) * 16));
            MMA16816(acc_o[0], a0, a1, a2, a3, r0, r2);
            MMA16816(acc_o[1], a0, a1, a2, a3, r1, r3);
        }
        __syncthreads();
    }

    // rowsums
    rs0 += __shfl_xor_sync(0xffffffffu, rs0, 1);
    rs0 += __shfl_xor_sync(0xffffffffu, rs0, 2);
    rs1 += __shfl_xor_sync(0xffffffffu, rs1, 1);
    rs1 += __shfl_xor_sync(0xffffffffu, rs1, 2);
    if (tg == 0) {
        rs[(wm * 16 + gq_) * 2 + wn] = rs0;
        rs[(wm * 16 + gq_ + 8) * 2 + wn] = rs1;
    }

    // stage O^T (reuse P region)
    float* Ost = (float*)(sm + AOFF_P);
#pragma unroll
    for (int t = 0; t < 2; t++) {
        int qc = vn * 16 + t * 8 + tg * 2;
        int d0 = vm * 16 + gq_;
        Ost[d0 * 65 + qc]     = acc_o[t][0];
        Ost[d0 * 65 + qc + 1] = acc_o[t][1];
        Ost[(d0 + 8) * 65 + qc]     = acc_o[t][2];
        Ost[(d0 + 8) * 65 + qc + 1] = acc_o[t][3];
    }
    __syncthreads();

    {
        int q = tid >> 2, ds = (tid & 3) * 8;
        int gq = q0 + q;
        if (gq < NTOK) {
            float inv = __frcp_rn(rs[q * 2] + rs[q * 2 + 1]);
            __nv_bfloat16 o[8];
#pragma unroll
            for (int u = 0; u < 8; u++)
                o[u] = __float2bfloat16(Ost[(ds + u) * 65 + q] * inv);
            *(uint4*)(out + (size_t)(w * NTOK + gq) * CDIM + h * HD + ds) = *(uint4*)o;
        }
    }
}

// ---------------- reverse + residual + LN2 ----------------
__global__ __launch_bounds__(CDIM) void ln2res_kernel(const float* __restrict__ x,
                                                      const float* __restrict__ proj,
                                                      const float* __restrict__ g,
                                                      const float* __restrict__ b,
                                                      float* __restrict__ xres,
                                                      __nv_bfloat16* __restrict__ ln2o) {
    __shared__ float red[12];
    int t = blockIdx.x;
    int c = threadIdx.x;
    int row = token_to_winrow(t);
    float v = x[(size_t)t * CDIM + c] + proj[(size_t)row * CDIM + c];
    xres[(size_t)t * CDIM + c] = v;

    float s  = warpSum(v);
    float s2 = warpSum(v * v);
    int w = c >> 5;
    if ((c & 31) == 0) { red[w] = s; red[6 + w] = s2; }
    __syncthreads();
    float ts = 0.f, ts2 = 0.f;
#pragma unroll
    for (int i = 0; i < 6; i++) { ts += red[i]; ts2 += red[6 + i]; }
    float mean = ts * (1.0f / CDIM);
    float var  = ts2 * (1.0f / CDIM) - mean * mean;
    ln2o[(size_t)t * CDIM + c] = __float2bfloat16((v - mean) * rsqrtf(var + 1e-5f) * g[c] + b[c]);
}

// ---------------- launch ----------------
extern "C" void kernel_launch(void* const* d_in, const int* in_sizes, int n_in,
                              void* d_out, int out_size) {
    (void)in_sizes; (void)n_in; (void)out_size;
    const float* x       = (const float*)d_in[0];
    const float* table   = (const float*)d_in[3];
    const float* n1g     = (const float*)d_in[4];
    const float* n1b     = (const float*)d_in[5];
    const float* qkv_w   = (const float*)d_in[6];
    const float* qkv_b   = (const float*)d_in[7];
    const float* proj_w  = (const float*)d_in[8];
    const float* proj_b  = (const float*)d_in[9];
    const float* n2g     = (const float*)d_in[10];
    const float* n2b     = (const float*)d_in[11];
    const float* fc1_w   = (const float*)d_in[12];
    const float* fc1_b   = (const float*)d_in[13];
    const float* fc2_w   = (const float*)d_in[14];
    const float* fc2_b   = (const float*)d_in[15];
    float* out = (float*)d_out;

    __nv_bfloat16 *xwb, *qkvb, *attnb, *ln2b, *h1b, *wqkv, *wproj, *wfc1, *wfc2, *comb;
    float *proj, *xres;
    cudaGetSymbolAddress((void**)&xwb,   g_xwb);
    cudaGetSymbolAddress((void**)&qkvb,  g_qkvb);
    cudaGetSymbolAddress((void**)&attnb, g_attnb);
    cudaGetSymbolAddress((void**)&proj,  g_proj);
    cudaGetSymbolAddress((void**)&xres,  g_xres);
    cudaGetSymbolAddress((void**)&ln2b,  g_ln2b);
    cudaGetSymbolAddress((void**)&h1b,   g_h1b);
    cudaGetSymbolAddress((void**)&wqkv,  g_wqkv);
    cudaGetSymbolAddress((void**)&wproj, g_wproj);
    cudaGetSymbolAddress((void**)&wfc1,  g_wfc1);
    cudaGetSymbolAddress((void**)&wfc2,  g_wfc2);
    cudaGetSymbolAddress((void**)&comb,  g_comb);

    cudaFuncSetAttribute(attn_tc_kernel, cudaFuncAttributeMaxDynamicSharedMemorySize,
                         ATTN_SMEM_BYTES);
    cudaFuncSetAttribute(gemm_mma_kernel<0>, cudaFuncAttributeMaxDynamicSharedMemorySize, GEMM_SMEM_BYTES);
    cudaFuncSetAttribute(gemm_mma_kernel<1>, cudaFuncAttributeMaxDynamicSharedMemorySize, GEMM_SMEM_BYTES);
    cudaFuncSetAttribute(gemm_mma_kernel<2>, cudaFuncAttributeMaxDynamicSharedMemorySize, GEMM_SMEM_BYTES);
    cudaFuncSetAttribute(gemm_mma_kernel<3>, cudaFuncAttributeMaxDynamicSharedMemorySize, GEMM_SMEM_BYTES);

    const int n0 = 3 * CDIM * CDIM, n1 = CDIM * CDIM, n2 = HID * CDIM, n3 = CDIM * HID;
    cvt4_kernel<<<(n0 + n1 + n2 + n3 + 255) / 256, 256>>>(
        qkv_w, wqkv, n0, proj_w, wproj, n1, fc1_w, wfc1, n2, fc2_w, wfc2, n3);
    comb_pre_kernel<<<(COMB_ELEMS + 255) / 256, 256>>>(table, comb);

    ln1_kernel<<<TOK, CDIM>>>(x, n1g, n1b, xwb);
    gemm_mma_kernel<3><<<dim3(576 / BN, TOK / BM), 256, GEMM_SMEM_BYTES>>>(
        xwb, wqkv, qkv_b, nullptr, qkvb, CDIM, 3 * CDIM);
    attn_tc_kernel<<<dim3(TOTWIN * HEADS, NCH), 256, ATTN_SMEM_BYTES>>>(qkvb, comb, attnb);
    gemm_mma_kernel<0><<<dim3(CDIM / BN, TOK / BM), 256, GEMM_SMEM_BYTES>>>(
        attnb, wproj, proj_b, nullptr, proj, CDIM, CDIM);
    ln2res_kernel<<<TOK, CDIM>>>(x, proj, n2g, n2b, xres, ln2b);
    gemm_mma_kernel<1><<<dim3(HID / BN, TOK / BM), 256, GEMM_SMEM_BYTES>>>(
        ln2b, wfc1, fc1_b, nullptr, h1b, CDIM, HID);
    gemm_mma_kernel<2><<<dim3(CDIM / BN, TOK / BM), 256, GEMM_SMEM_BYTES>>>(
        h1b, wfc2, fc2_b, xres, out, HID, CDIM);
}

// round 7
// speedup vs baseline: 9.3658x; 1.2415x over previous
#include <cuda_runtime.h>
#include <cuda_bf16.h>
#include <math.h>
#include <stdint.h>

// ---------------- problem constants ----------------
#define BATCH   2
#define DSZ     28
#define WS      7
#define SHIFT_  3
#define CDIM    192
#define HEADS   6
#define HD      32
#define NTOK    343
#define NWIN    64
#define TOTWIN  128
#define TOK     43904
#define HID     768
#define SCALE   0.17677669529663687f

// GEMM tiling
#define BM      128
#define BN      64
#define KB      64
#define GEMM_SMEM_BYTES 73728

// attention tiling
#define QT      64
#define NC      64
#define KPAD    384
#define NCH     6
#define QPITCH  80
#define KPITCH  80
#define VPITCH  784
#define PPITCH  144
#define CPITCH  344
// smem offsets (bytes)
#define AOFF_K   0
#define AOFF_V   30720
#define AOFF_Q   55808
#define AOFF_P   60928
#define AOFF_RS  70144
#define ATTN_SMEM_BYTES 70656

#define COMB_ELEMS (48 * NTOK * CPITCH)

// ---------------- scratch (device globals) ----------------
__device__ __nv_bfloat16 g_xwb [TOK * CDIM];
__device__ __nv_bfloat16 g_qkvb[TOK * 3 * CDIM];
__device__ __nv_bfloat16 g_attnb[TOK * CDIM];
__device__ float         g_proj[TOK * CDIM];
__device__ float         g_xres[TOK * CDIM];
__device__ __nv_bfloat16 g_ln2b[TOK * CDIM];
__device__ __nv_bfloat16 g_h1b [TOK * HID];
__device__ __nv_bfloat16 g_wqkv[3 * CDIM * CDIM];
__device__ __nv_bfloat16 g_wproj[CDIM * CDIM];
__device__ __nv_bfloat16 g_wfc1[HID * CDIM];
__device__ __nv_bfloat16 g_wfc2[CDIM * HID];
__device__ __nv_bfloat16 g_comb[COMB_ELEMS];   // [head][maskclass][row][colpad]

// ---------------- helpers ----------------
__device__ __forceinline__ uint32_t s2u(const void* p) {
    uint32_t r;
    asm("{ .reg .u64 t; cvta.to.shared.u64 t, %1; cvt.u32.u64 %0, t; }" : "=r"(r) : "l"(p));
    return r;
}
__device__ __forceinline__ float warpSum(float v) {
#pragma unroll
    for (int o = 16; o; o >>= 1) v += __shfl_xor_sync(0xffffffffu, v, o);
    return v;
}
__device__ __forceinline__ int token_to_winrow(int t) {
    int b   = t / (DSZ * DSZ * DSZ);
    int rem = t - b * (DSZ * DSZ * DSZ);
    int dd  = rem / (DSZ * DSZ);
    int hh  = (rem / DSZ) % DSZ;
    int ww  = rem % DSZ;
    int i = (dd + DSZ - SHIFT_) % DSZ;
    int j = (hh + DSZ - SHIFT_) % DSZ;
    int k = (ww + DSZ - SHIFT_) % DSZ;
    int win = (i / WS) * 16 + (j / WS) * 4 + (k / WS);
    int n   = (i % WS) * 49 + (j % WS) * 7 + (k % WS);
    return (b * NWIN + win) * NTOK + n;
}

#define CP_ASYNC16(dst_u32, src_ptr) \
    asm volatile("cp.async.cg.shared.global [%0], [%1], 16;" :: "r"(dst_u32), "l"(src_ptr))
#define CP_COMMIT() asm volatile("cp.async.commit_group;")
#define CP_WAIT(n)  asm volatile("cp.async.wait_group %0;" :: "n"(n))

#define LDMX4(r0, r1, r2, r3, addr) \
    asm volatile("ldmatrix.sync.aligned.m8n8.x4.shared.b16 {%0,%1,%2,%3}, [%4];" \
                 : "=r"(r0), "=r"(r1), "=r"(r2), "=r"(r3) : "r"(addr))

#define MMA16816(d, a0, a1, a2, a3, b0, b1) \
    asm volatile("mma.sync.aligned.m16n8k16.row.col.f32.bf16.bf16.f32 " \
                 "{%0,%1,%2,%3}, {%4,%5,%6,%7}, {%8,%9}, {%0,%1,%2,%3};" \
                 : "+f"((d)[0]), "+f"((d)[1]), "+f"((d)[2]), "+f"((d)[3]) \
                 : "r"(a0), "r"(a1), "r"(a2), "r"(a3), "r"(b0), "r"(b1))

// ---------------- merged weight conversion ----------------
__global__ void cvt4_kernel(const float* __restrict__ s0, __nv_bfloat16* __restrict__ d0, int n0,
                            const float* __restrict__ s1, __nv_bfloat16* __restrict__ d1, int n1,
                            const float* __restrict__ s2, __nv_bfloat16* __restrict__ d2, int n2,
                            const float* __restrict__ s3, __nv_bfloat16* __restrict__ d3, int n3) {
    int i = blockIdx.x * 256 + threadIdx.x;
    if (i < n0) { d0[i] = __float2bfloat16(s0[i]); return; }
    i -= n0;
    if (i < n1) { d1[i] = __float2bfloat16(s1[i]); return; }
    i -= n1;
    if (i < n2) { d2[i] = __float2bfloat16(s2[i]); return; }
    i -= n2;
    if (i < n3) { d3[i] = __float2bfloat16(s3[i]); }
}

// ---------------- combined bias+mask precompute ----------------
__global__ void comb_pre_kernel(const float* __restrict__ table,
                                __nv_bfloat16* __restrict__ comb) {
    int idx = blockIdx.x * 256 + threadIdx.x;
    if (idx >= COMB_ELEMS) return;
    int col  = idx % CPITCH;
    int rest = idx / CPITCH;
    int row  = rest % NTOK;
    int hc   = rest / NTOK;
    int h = hc >> 3, cls = hc & 7;
    float val = -100.f;
    if (col < NTOK) {
        int i3 = row / 49, j3 = (row / 7) % 7, k3 = row % 7;
        int ci = col / 49, cj = (col / 7) % 7, ck = col % 7;
        int rel = (i3 - ci + 6) * 169 + (j3 - cj + 6) * 13 + (k3 - ck + 6);
        val = table[rel * HEADS + h];
        bool diff = ((cls & 4) && ((i3 < 4) != (ci < 4))) ||
                    ((cls & 2) && ((j3 < 4) != (cj < 4))) ||
                    ((cls & 1) && ((k3 < 4) != (ck < 4)));
        if (diff) val -= 100.f;
    }
    comb[idx] = __float2bfloat16(val);
}

// ---------------- LN1 + shift + partition: warp-per-token ----------------
__global__ __launch_bounds__(256) void ln1_kernel(const float* __restrict__ x,
                                                  const float* __restrict__ g,
                                                  const float* __restrict__ b,
                                                  __nv_bfloat16* __restrict__ xw) {
    int t = blockIdx.x * 8 + (threadIdx.x >> 5);
    int lane = threadIdx.x & 31;
    const float* xp = x + (size_t)t * CDIM;
    float v[6];
    float s = 0.f, s2 = 0.f;
#pragma unroll
    for (int i = 0; i < 6; i++) {
        v[i] = xp[lane + i * 32];
        s += v[i]; s2 += v[i] * v[i];
    }
    s = warpSum(s); s2 = warpSum(s2);
    float mean = s * (1.0f / CDIM);
    float rstd = rsqrtf(s2 * (1.0f / CDIM) - mean * mean + 1e-5f);
    int row = token_to_winrow(t);
    __nv_bfloat16* op = xw + (size_t)row * CDIM;
#pragma unroll
    for (int i = 0; i < 6; i++) {
        int c = lane + i * 32;
        op[c] = __float2bfloat16((v[i] - mean) * rstd * g[c] + b[c]);
    }
}

// ---------------- GEMM tile loader ----------------
__device__ __forceinline__ void gemm_issue(const __nv_bfloat16* __restrict__ A,
                                           const __nv_bfloat16* __restrict__ Wt,
                                           int bm, int bn, int Ktot, int lr, int lc8,
                                           char* bA, char* bB, int k0) {
#pragma unroll
    for (int rr = 0; rr < 4; rr++) {
        int r = lr + rr * 32;
        uint32_t off = (uint32_t)(r * 128 + lc8 * 2);
        off ^= (off >> 3) & 0x70;
        CP_ASYNC16(s2u(bA + off), A + (size_t)(bm + r) * Ktot + k0 + lc8);
    }
#pragma unroll
    for (int rr = 0; rr < 2; rr++) {
        int br = lr + rr * 32;
        uint32_t off = (uint32_t)(br * 128 + lc8 * 2);
        off ^= (off >> 3) & 0x70;
        CP_ASYNC16(s2u(bB + off), Wt + (size_t)(bn + br) * Ktot + k0 + lc8);
    }
    CP_COMMIT();
}

// ---------------- HMMA bf16 GEMM ----------------
// FULLK: entire K (=192) resident, single barrier. Otherwise 3-stage pipeline.
template <int EPI, bool FULLK>
__global__ __launch_bounds__(256)
void gemm_mma_kernel(const __nv_bfloat16* __restrict__ A,
                     const __nv_bfloat16* __restrict__ Wt,
                     const float* __restrict__ bias,
                     const float* __restrict__ resid,
                     void* __restrict__ Cv, int Ktot, int Ntot)
{
    extern __shared__ __align__(1024) char dsm[];
    char* bufA[3] = {dsm, dsm + 16384, dsm + 32768};
    char* bufB[3] = {dsm + 49152, dsm + 57344, dsm + 65536};

    const int tid = threadIdx.x;
    const int lane = tid & 31;
    const int wid = tid >> 5;
    const int wm = (wid & 3) * 32;
    const int wn = (wid >> 2) * 32;
    const int bm = blockIdx.y * BM;
    const int bn = blockIdx.x * BN;

    float acc[2][4][4];
#pragma unroll
    for (int a = 0; a < 2; a++)
#pragma unroll
        for (int b = 0; b < 4; b++)
#pragma unroll
            for (int c = 0; c < 4; c++) acc[a][b][c] = 0.f;

    const int lr = tid >> 3;
    const int lc8 = (tid & 7) * 8;

    if (FULLK) {
        // all three K-chunks resident; one barrier; 12 uninterrupted k-steps
#pragma unroll
        for (int ch = 0; ch < 3; ch++)
            gemm_issue(A, Wt, bm, bn, Ktot, lr, lc8, bufA[ch], bufB[ch], ch * KB);
        CP_WAIT(0);
        __syncthreads();
#pragma unroll
        for (int ks = 0; ks < 12; ks++) {
            const int chunk = ks >> 2, kk = ks & 3;
            const uint32_t sA = s2u(bufA[chunk]);
            const uint32_t sB = s2u(bufB[chunk]);
            uint32_t a0[2], a1[2], a2[2], a3[2];
#pragma unroll
            for (int mi = 0; mi < 2; mi++) {
                uint32_t off = (uint32_t)((wm + mi * 16 + (lane & 15)) * 128 + kk * 32 + (lane >> 4) * 16);
                off ^= (off >> 3) & 0x70;
                LDMX4(a0[mi], a1[mi], a2[mi], a3[mi], sA + off);
            }
#pragma unroll
            for (int nj = 0; nj < 2; nj++) {
                uint32_t off = (uint32_t)((wn + nj * 16 + (lane & 15)) * 128 + kk * 32 + (lane >> 4) * 16);
                off ^= (off >> 3) & 0x70;
                uint32_t r0, r1, r2, r3;
                LDMX4(r0, r1, r2, r3, sB + off);
#pragma unroll
                for (int mi = 0; mi < 2; mi++) {
                    MMA16816(acc[mi][2 * nj], a0[mi], a1[mi], a2[mi], a3[mi], r0, r2);
                    MMA16816(acc[mi][2 * nj + 1], a0[mi], a1[mi], a2[mi], a3[mi], r1, r3);
                }
            }
        }
    } else {
        const int nch = Ktot / KB;
        gemm_issue(A, Wt, bm, bn, Ktot, lr, lc8, bufA[0], bufB[0], 0);
        gemm_issue(A, Wt, bm, bn, Ktot, lr, lc8, bufA[1], bufB[1], KB);
        for (int ch = 0; ch < nch; ch++) {
            if (ch + 2 < nch)
                gemm_issue(A, Wt, bm, bn, Ktot, lr, lc8,
                           bufA[(ch + 2) % 3], bufB[(ch + 2) % 3], (ch + 2) * KB);
            const int rem = nch - ch - 1;
            if (rem >= 2)      CP_WAIT(2);
            else if (rem == 1) CP_WAIT(1);
            else               CP_WAIT(0);
            __syncthreads();

            const uint32_t sA = s2u(bufA[ch % 3]);
            const uint32_t sB = s2u(bufB[ch % 3]);
#pragma unroll
            for (int ks = 0; ks < KB / 16; ks++) {
                uint32_t a0[2], a1[2], a2[2], a3[2];
#pragma unroll
                for (int mi = 0; mi < 2; mi++) {
                    uint32_t off = (uint32_t)((wm + mi * 16 + (lane & 15)) * 128 + ks * 32 + (lane >> 4) * 16);
                    off ^= (off >> 3) & 0x70;
                    LDMX4(a0[mi], a1[mi], a2[mi], a3[mi], sA + off);
                }
#pragma unroll
                for (int nj = 0; nj < 2; nj++) {
                    uint32_t off = (uint32_t)((wn + nj * 16 + (lane & 15)) * 128 + ks * 32 + (lane >> 4) * 16);
                    off ^= (off >> 3) & 0x70;
                    uint32_t r0, r1, r2, r3;
                    LDMX4(r0, r1, r2, r3, sB + off);
#pragma unroll
                    for (int mi = 0; mi < 2; mi++) {
                        MMA16816(acc[mi][2 * nj], a0[mi], a1[mi], a2[mi], a3[mi], r0, r2);
                        MMA16816(acc[mi][2 * nj + 1], a0[mi], a1[mi], a2[mi], a3[mi], r1, r3);
                    }
                }
            }
            __syncthreads();
        }
    }

    const int gq = lane >> 2;
    const int tg = lane & 3;
#pragma unroll
    for (int mi = 0; mi < 2; mi++) {
#pragma unroll
        for (int ni = 0; ni < 4; ni++) {
            int col = bn + wn + ni * 8 + tg * 2;
            float bia0 = bias[col], bia1 = bias[col + 1];
#pragma unroll
            for (int half = 0; half < 2; half++) {
                int row = bm + wm + mi * 16 + gq + half * 8;
                float v0 = acc[mi][ni][half * 2 + 0] + bia0;
                float v1 = acc[mi][ni][half * 2 + 1] + bia1;
                size_t oi = (size_t)row * Ntot + col;
                if (EPI == 1) {
                    v0 = 0.5f * v0 * (1.0f + erff(v0 * 0.7071067811865476f));
                    v1 = 0.5f * v1 * (1.0f + erff(v1 * 0.7071067811865476f));
                    __nv_bfloat162 p;
                    p.x = __float2bfloat16(v0); p.y = __float2bfloat16(v1);
                    *(__nv_bfloat162*)((__nv_bfloat16*)Cv + oi) = p;
                } else if (EPI == 2) {
                    float2 rv = *(const float2*)(resid + oi);
                    float2 o; o.x = v0 + rv.x; o.y = v1 + rv.y;
                    *(float2*)((float*)Cv + oi) = o;
                } else if (EPI == 3) {
                    __nv_bfloat162 p;
                    p.x = __float2bfloat16(v0); p.y = __float2bfloat16(v1);
                    *(__nv_bfloat162*)((__nv_bfloat16*)Cv + oi) = p;
                } else {
                    float2 o; o.x = v0; o.y = v1;
                    *(float2*)((float*)Cv + oi) = o;
                }
            }
        }
    }
}

// ---------------- tensor-core attention ----------------
__global__ __launch_bounds__(256, 3) void attn_tc_kernel(
    const __nv_bfloat16* __restrict__ qkv, const __nv_bfloat16* __restrict__ comb,
    __nv_bfloat16* __restrict__ out)
{
    extern __shared__ __align__(1024) char sm[];
    const uint32_t uK = s2u(sm + AOFF_K);
    const uint32_t uV = s2u(sm + AOFF_V);
    const uint32_t uQ = s2u(sm + AOFF_Q);
    const uint32_t uP = s2u(sm + AOFF_P);
    float* rs = (float*)(sm + AOFF_RS);

    const int bx = blockIdx.x;
    const int w  = bx / HEADS;
    const int h  = bx - w * HEADS;
    const int mw = w % NWIN;
    const int wd = mw >> 4, wh = (mw >> 2) & 3, ww = mw & 3;
    const int cls = ((wd == 3) << 2) | ((wh == 3) << 1) | (ww == 3);
    const int q0 = blockIdx.y * QT;
    const int tid = threadIdx.x;
    const int lane = tid & 31;
    const int wid = tid >> 5;

    const __nv_bfloat16* base = qkv + (size_t)w * NTOK * (3 * CDIM);

    for (int idx = tid; idx < KPAD * 4; idx += 256) {
        int j = idx >> 2, s = idx & 3;
        uint4 v = make_uint4(0, 0, 0, 0);
        if (j < NTOK) v = *(const uint4*)(base + (size_t)j * (3 * CDIM) + CDIM + h * HD + s * 8);
        *(uint4*)(sm + AOFF_K + j * KPITCH + s * 16) = v;
    }
    for (int idx = tid; idx < QT * 4; idx += 256) {
        int r = idx >> 2, s = idx & 3;
        int gq = q0 + r;
        uint4 v = make_uint4(0, 0, 0, 0);
        if (gq < NTOK) v = *(const uint4*)(base + (size_t)gq * (3 * CDIM) + h * HD + s * 8);
        *(uint4*)(sm + AOFF_Q + r * QPITCH + s * 16) = v;
    }
    for (int jp = tid; jp < KPAD / 2; jp += 256) {
        int j0 = jp * 2;
        __nv_bfloat16 ta[32], tb[32];
        if (j0 < NTOK) {
            const __nv_bfloat16* vp = base + (size_t)j0 * (3 * CDIM) + 2 * CDIM + h * HD;
#pragma unroll
            for (int s = 0; s < 4; s++) *(uint4*)(ta + s * 8) = *(const uint4*)(vp + s * 8);
        } else {
#pragma unroll
            for (int d = 0; d < 32; d++) ta[d] = __float2bfloat16(0.f);
        }
        if (j0 + 1 < NTOK) {
            const __nv_bfloat16* vp = base + (size_t)(j0 + 1) * (3 * CDIM) + 2 * CDIM + h * HD;
#pragma unroll
            for (int s = 0; s < 4; s++) *(uint4*)(tb + s * 8) = *(const uint4*)(vp + s * 8);
        } else {
#pragma unroll
            for (int d = 0; d < 32; d++) tb[d] = __float2bfloat16(0.f);
        }
#pragma unroll
        for (int d = 0; d < 32; d++) {
            __nv_bfloat162 p; p.x = ta[d]; p.y = tb[d];
            *(__nv_bfloat162*)(sm + AOFF_V + d * VPITCH + j0 * 2) = p;
        }
    }
    __syncthreads();

    const int wm = wid & 3, wn = wid >> 2;
    const int vm = wid & 1, vn = wid >> 1;
    const int gq_ = lane >> 2, tg = lane & 3;

    float acc_o[2][4];
#pragma unroll
    for (int t = 0; t < 2; t++)
#pragma unroll
        for (int c = 0; c < 4; c++) acc_o[t][c] = 0.f;
    float rs0 = 0.f, rs1 = 0.f;

    const int r0g = q0 + wm * 16 + gq_;
    const int r1g = r0g + 8;
    const bool v0 = (r0g < NTOK);
    const bool v1 = (r1g < NTOK);
    const __nv_bfloat16* cb = comb + (size_t)(h * 8 + cls) * NTOK * CPITCH;
    const __nv_bfloat16* c0p = cb + (size_t)r0g * CPITCH;
    const __nv_bfloat16* c1p = cb + (size_t)r1g * CPITCH;

    for (int ch = 0; ch < NCH; ch++) {
        const int j0 = ch * NC;
        float acc[4][4];
#pragma unroll
        for (int t = 0; t < 4; t++)
#pragma unroll
            for (int c = 0; c < 4; c++) acc[t][c] = 0.f;

#pragma unroll
        for (int ks = 0; ks < 2; ks++) {
            uint32_t a0, a1, a2, a3;
            LDMX4(a0, a1, a2, a3,
                  uQ + (uint32_t)((wm * 16 + (lane & 15)) * QPITCH + ks * 32 + (lane >> 4) * 16));
#pragma unroll
            for (int nj = 0; nj < 2; nj++) {
                uint32_t r0, r1, r2, r3;
                LDMX4(r0, r1, r2, r3,
                      uK + (uint32_t)((j0 + wn * 32 + nj * 16 + (lane & 15)) * KPITCH + ks * 32 + (lane >> 4) * 16));
                MMA16816(acc[2 * nj], a0, a1, a2, a3, r0, r2);
                MMA16816(acc[2 * nj + 1], a0, a1, a2, a3, r1, r3);
            }
        }

#pragma unroll
        for (int ti = 0; ti < 4; ti++) {
            int jl = wn * 32 + (ti >> 1) * 16 + (ti & 1) * 8 + tg * 2;
            int ja = j0 + jl;
            float e00 = 0.f, e01 = 0.f, e10 = 0.f, e11 = 0.f;
            if (ja < NTOK) {
                if (v0) {
                    __nv_bfloat162 bp = *(const __nv_bfloat162*)(c0p + ja);
                    e00 = __expf(fmaf(acc[ti][0], SCALE, __bfloat162float(bp.x)));
                    e01 = __expf(fmaf(acc[ti][1], SCALE, __bfloat162float(bp.y)));
                }
                if (v1) {
                    __nv_bfloat162 bp = *(const __nv_bfloat162*)(c1p + ja);
                    e10 = __expf(fmaf(acc[ti][2], SCALE, __bfloat162float(bp.x)));
                    e11 = __expf(fmaf(acc[ti][3], SCALE, __bfloat162float(bp.y)));
                }
            }
            rs0 += e00 + e01;
            rs1 += e10 + e11;
            __nv_bfloat162 p0, p1;
            p0.x = __float2bfloat16(e00); p0.y = __float2bfloat16(e01);
            p1.x = __float2bfloat16(e10); p1.y = __float2bfloat16(e11);
            int rloc0 = wm * 16 + gq_;
            *(__nv_bfloat162*)(sm + AOFF_P + rloc0 * PPITCH + jl * 2) = p0;
            *(__nv_bfloat162*)(sm + AOFF_P + (rloc0 + 8) * PPITCH + jl * 2) = p1;
        }
        __syncthreads();

#pragma unroll
        for (int kk = 0; kk < 4; kk++) {
            uint32_t a0, a1, a2, a3;
            LDMX4(a0, a1, a2, a3,
                  uV + (uint32_t)((vm * 16 + (lane & 15)) * VPITCH + j0 * 2 + kk * 32 + (lane >> 4) * 16));
            uint32_t r0, r1, r2, r3;
            LDMX4(r0, r1, r2, r3,
                  uP + (uint32_t)((vn * 16 + (lane & 15)) * PPITCH + kk * 32 + (lane >> 4) * 16));
            MMA16816(acc_o[0], a0, a1, a2, a3, r0, r2);
            MMA16816(acc_o[1], a0, a1, a2, a3, r1, r3);
        }
        __syncthreads();
    }

    rs0 += __shfl_xor_sync(0xffffffffu, rs0, 1);
    rs0 += __shfl_xor_sync(0xffffffffu, rs0, 2);
    rs1 += __shfl_xor_sync(0xffffffffu, rs1, 1);
    rs1 += __shfl_xor_sync(0xffffffffu, rs1, 2);
    if (tg == 0) {
        rs[(wm * 16 + gq_) * 2 + wn] = rs0;
        rs[(wm * 16 + gq_ + 8) * 2 + wn] = rs1;
    }

    float* Ost = (float*)(sm + AOFF_P);
#pragma unroll
    for (int t = 0; t < 2; t++) {
        int qc = vn * 16 + t * 8 + tg * 2;
        int d0 = vm * 16 + gq_;
        Ost[d0 * 65 + qc]     = acc_o[t][0];
        Ost[d0 * 65 + qc + 1] = acc_o[t][1];
        Ost[(d0 + 8) * 65 + qc]     = acc_o[t][2];
        Ost[(d0 + 8) * 65 + qc + 1] = acc_o[t][3];
    }
    __syncthreads();

    {
        int q = tid >> 2, ds = (tid & 3) * 8;
        int gq = q0 + q;
        if (gq < NTOK) {
            float inv = __frcp_rn(rs[q * 2] + rs[q * 2 + 1]);
            __nv_bfloat16 o[8];
#pragma unroll
            for (int u = 0; u < 8; u++)
                o[u] = __float2bfloat16(Ost[(ds + u) * 65 + q] * inv);
            *(uint4*)(out + (size_t)(w * NTOK + gq) * CDIM + h * HD + ds) = *(uint4*)o;
        }
    }
}

// ---------------- reverse + residual + LN2: warp-per-token ----------------
__global__ __launch_bounds__(256) void ln2res_kernel(const float* __restrict__ x,
                                                     const float* __restrict__ proj,
                                                     const float* __restrict__ g,
                                                     const float* __restrict__ b,
                                                     float* __restrict__ xres,
                                                     __nv_bfloat16* __restrict__ ln2o) {
    int t = blockIdx.x * 8 + (threadIdx.x >> 5);
    int lane = threadIdx.x & 31;
    int row = token_to_winrow(t);
    const float* xp = x + (size_t)t * CDIM;
    const float* pp = proj + (size_t)row * CDIM;
    float* rp = xres + (size_t)t * CDIM;
    float v[6];
    float s = 0.f, s2 = 0.f;
#pragma unroll
    for (int i = 0; i < 6; i++) {
        int c = lane + i * 32;
        v[i] = xp[c] + pp[c];
        rp[c] = v[i];
        s += v[i]; s2 += v[i] * v[i];
    }
    s = warpSum(s); s2 = warpSum(s2);
    float mean = s * (1.0f / CDIM);
    float rstd = rsqrtf(s2 * (1.0f / CDIM) - mean * mean + 1e-5f);
    __nv_bfloat16* op = ln2o + (size_t)t * CDIM;
#pragma unroll
    for (int i = 0; i < 6; i++) {
        int c = lane + i * 32;
        op[c] = __float2bfloat16((v[i] - mean) * rstd * g[c] + b[c]);
    }
}

// ---------------- launch ----------------
extern "C" void kernel_launch(void* const* d_in, const int* in_sizes, int n_in,
                              void* d_out, int out_size) {
    (void)in_sizes; (void)n_in; (void)out_size;
    const float* x       = (const float*)d_in[0];
    const float* table   = (const float*)d_in[3];
    const float* n1g     = (const float*)d_in[4];
    const float* n1b     = (const float*)d_in[5];
    const float* qkv_w   = (const float*)d_in[6];
    const float* qkv_b   = (const float*)d_in[7];
    const float* proj_w  = (const float*)d_in[8];
    const float* proj_b  = (const float*)d_in[9];
    const float* n2g     = (const float*)d_in[10];
    const float* n2b     = (const float*)d_in[11];
    const float* fc1_w   = (const float*)d_in[12];
    const float* fc1_b   = (const float*)d_in[13];
    const float* fc2_w   = (const float*)d_in[14];
    const float* fc2_b   = (const float*)d_in[15];
    float* out = (float*)d_out;

    __nv_bfloat16 *xwb, *qkvb, *attnb, *ln2b, *h1b, *wqkv, *wproj, *wfc1, *wfc2, *comb;
    float *proj, *xres;
    cudaGetSymbolAddress((void**)&xwb,   g_xwb);
    cudaGetSymbolAddress((void**)&qkvb,  g_qkvb);
    cudaGetSymbolAddress((void**)&attnb, g_attnb);
    cudaGetSymbolAddress((void**)&proj,  g_proj);
    cudaGetSymbolAddress((void**)&xres,  g_xres);
    cudaGetSymbolAddress((void**)&ln2b,  g_ln2b);
    cudaGetSymbolAddress((void**)&h1b,   g_h1b);
    cudaGetSymbolAddress((void**)&wqkv,  g_wqkv);
    cudaGetSymbolAddress((void**)&wproj, g_wproj);
    cudaGetSymbolAddress((void**)&wfc1,  g_wfc1);
    cudaGetSymbolAddress((void**)&wfc2,  g_wfc2);
    cudaGetSymbolAddress((void**)&comb,  g_comb);

    cudaFuncSetAttribute(attn_tc_kernel, cudaFuncAttributeMaxDynamicSharedMemorySize,
                         ATTN_SMEM_BYTES);
    cudaFuncSetAttribute((gemm_mma_kernel<3, true>), cudaFuncAttributeMaxDynamicSharedMemorySize, GEMM_SMEM_BYTES);
    cudaFuncSetAttribute((gemm_mma_kernel<0, true>), cudaFuncAttributeMaxDynamicSharedMemorySize, GEMM_SMEM_BYTES);
    cudaFuncSetAttribute((gemm_mma_kernel<1, true>), cudaFuncAttributeMaxDynamicSharedMemorySize, GEMM_SMEM_BYTES);
    cudaFuncSetAttribute((gemm_mma_kernel<2, false>), cudaFuncAttributeMaxDynamicSharedMemorySize, GEMM_SMEM_BYTES);

    const int n0 = 3 * CDIM * CDIM, n1 = CDIM * CDIM, n2 = HID * CDIM, n3 = CDIM * HID;
    cvt4_kernel<<<(n0 + n1 + n2 + n3 + 255) / 256, 256>>>(
        qkv_w, wqkv, n0, proj_w, wproj, n1, fc1_w, wfc1, n2, fc2_w, wfc2, n3);
    comb_pre_kernel<<<(COMB_ELEMS + 255) / 256, 256>>>(table, comb);

    ln1_kernel<<<TOK / 8, 256>>>(x, n1g, n1b, xwb);
    gemm_mma_kernel<3, true><<<dim3(576 / BN, TOK / BM), 256, GEMM_SMEM_BYTES>>>(
        xwb, wqkv, qkv_b, nullptr, qkvb, CDIM, 3 * CDIM);
    attn_tc_kernel<<<dim3(TOTWIN * HEADS, NCH), 256, ATTN_SMEM_BYTES>>>(qkvb, comb, attnb);
    gemm_mma_kernel<0, true><<<dim3(CDIM / BN, TOK / BM), 256, GEMM_SMEM_BYTES>>>(
        attnb, wproj, proj_b, nullptr, proj, CDIM, CDIM);
    ln2res_kernel<<<TOK / 8, 256>>>(x, proj, n2g, n2b, xres, ln2b);
    gemm_mma_kernel<1, true><<<dim3(HID / BN, TOK / BM), 256, GEMM_SMEM_BYTES>>>(
        ln2b, wfc1, fc1_b, nullptr, h1b, CDIM, HID);
    gemm_mma_kernel<2, false><<<dim3(CDIM / BN, TOK / BM), 256, GEMM_SMEM_BYTES>>>(
        h1b, wfc2, fc2_b, xres, out, HID, CDIM);
}